// round 14
// baseline (speedup 1.0000x reference)
#include <cuda_runtime.h>
#include <cuda_bf16.h>
#include <math.h>
#include <stdint.h>

#define BB 2
#define SS 2048
#define HID 4096
#define NHQ 32
#define NHKV 8
#define HD 128
#define MR (BB*SS)          // 4096 rows
#define KVD (NHKV*HD)       // 1024
#define GRP (NHQ/NHKV)      // 4
#define GK 4096             // all GEMMs have K=4096

// ---------------- scratch (__device__ globals) ------------------------------
__device__ float g_Q[MR*HID];
__device__ float g_K[MR*KVD];
__device__ float g_cos[SS*(HD/2)];
__device__ float g_sin[SS*(HD/2)];
__device__ __nv_bfloat16 g_xh[MR*HID],  g_xl[MR*HID];
__device__ __nv_bfloat16 g_Wqh[HID*HID], g_Wql[HID*HID];   // [K,N] row-major
__device__ __nv_bfloat16 g_Wkh[HID*KVD], g_Wkl[HID*KVD];
__device__ __nv_bfloat16 g_Wvh[HID*KVD], g_Wvl[HID*KVD];
__device__ __nv_bfloat16 g_Woh[HID*HID], g_Wol[HID*HID];
__device__ __nv_bfloat16 g_Qh[MR*HID], g_Ql[MR*HID];
__device__ __nv_bfloat16 g_Kh[MR*KVD], g_Kl[MR*KVD];
__device__ __nv_bfloat16 g_Vh[MR*KVD], g_Vl[MR*KVD];
__device__ __nv_bfloat16 g_Ath[MR*HID], g_Atl[MR*HID];

// ---------------- PTX helpers (portable sm_80-era ops) ----------------------
__device__ __forceinline__ uint32_t su32(const void* p) {
    uint32_t a;
    asm("{ .reg .u64 t; cvta.to.shared.u64 t, %1; cvt.u32.u64 %0, t; }"
        : "=r"(a) : "l"(p));
    return a;
}
__device__ __forceinline__ void cp16(uint32_t sa, const void* g) {
    asm volatile("cp.async.cg.shared.global [%0], [%1], 16;\n" :: "r"(sa), "l"(g));
}
#define CP_COMMIT() asm volatile("cp.async.commit_group;\n")
#define LDSM_X4(r, a) \
    asm volatile("ldmatrix.sync.aligned.m8n8.x4.shared.b16 {%0,%1,%2,%3}, [%4];" \
        : "=r"((r)[0]), "=r"((r)[1]), "=r"((r)[2]), "=r"((r)[3]) : "r"(a))
#define LDSM_X4T(r, a) \
    asm volatile("ldmatrix.sync.aligned.m8n8.x4.trans.shared.b16 {%0,%1,%2,%3}, [%4];" \
        : "=r"((r)[0]), "=r"((r)[1]), "=r"((r)[2]), "=r"((r)[3]) : "r"(a))
#define MMA4(d, a, b0, b1) \
    asm volatile("mma.sync.aligned.m16n8k16.row.col.f32.bf16.bf16.f32 " \
        "{%0,%1,%2,%3},{%4,%5,%6,%7},{%8,%9},{%0,%1,%2,%3};" \
        : "+f"((d)[0]), "+f"((d)[1]), "+f"((d)[2]), "+f"((d)[3]) \
        : "r"((a)[0]), "r"((a)[1]), "r"((a)[2]), "r"((a)[3]), "r"(b0), "r"(b1))

__device__ __forceinline__ uint32_t swz256(uint32_t o) {   // 256B rows
    return o ^ (((o >> 8) & 7u) << 4);
}
__device__ __forceinline__ uint32_t swz128(uint32_t o) {   // 128B rows
    return o ^ (((o >> 7) & 7u) << 4);
}
__device__ __forceinline__ void pk2(float x, float y, uint32_t& hi, uint32_t& lo) {
    __nv_bfloat16 hx = __float2bfloat16(x), hy = __float2bfloat16(y);
    hi = ((uint32_t)*(uint16_t*)&hy << 16) | *(uint16_t*)&hx;
    __nv_bfloat16 lx = __float2bfloat16(x - __bfloat162float(hx));
    __nv_bfloat16 ly = __float2bfloat16(y - __bfloat162float(hy));
    lo = ((uint32_t)*(uint16_t*)&ly << 16) | *(uint16_t*)&lx;
}

// ---------------------------------------------------------------------------
// Split-bf16 tensor-core GEMM: C[M,N] = A[M,4096] @ B[4096,N]
// 3-pass (AhBh + AhBl + AlBh). CTA 128x128, BK=64, 3-stage, 512 threads,
// 16 warps (4/SMSP) of 32x32 warp tiles. Loads issued BEFORE the wait.
// L2 supertile swizzle (GROUP_M=8).
// ---------------------------------------------------------------------------
#define GEMM_SMEM 196608

__global__ void __launch_bounds__(512) gemm_bf16s(
    const __nv_bfloat16* __restrict__ Ah, const __nv_bfloat16* __restrict__ Al,
    const __nv_bfloat16* __restrict__ Bh, const __nv_bfloat16* __restrict__ Bl,
    float* __restrict__ Cf,
    __nv_bfloat16* __restrict__ Oh, __nv_bfloat16* __restrict__ Ol, int N)
{
    extern __shared__ __align__(1024) char smg[];
    const uint32_t sb = su32(smg);
    const int tid = threadIdx.x, w = tid >> 5, l = tid & 31;

    // ---- L2 supertile swizzle (GROUP_M = 8 m-blocks per column group) ----
    const int nbx = gridDim.x, nby = gridDim.y;
    int bid = blockIdx.y * nbx + blockIdx.x;
    const int GMg = 8;
    int grp   = bid / (GMg * nbx);
    int first = grp * GMg;
    int sz    = (nby - first) < GMg ? (nby - first) : GMg;
    int mb    = first + (bid % sz);
    int nb    = (bid % (GMg * nbx)) / sz;
    const int m0 = mb * 128, n0 = nb * 128;
    const int wm = (w & 3) * 32, wn = (w >> 2) * 32;

    auto loadChunk = [&](int c, int stg) {
        const uint32_t st = sb + (uint32_t)stg * 65536;
        const int k0 = c * 64;
        #pragma unroll
        for (int t = 0; t < 2; t++) {                 // A: [128 m][64 k], 128B rows
            int j = tid + t * 512;                    // 0..1023
            int r = j >> 3, cc = j & 7;
            uint32_t o = swz128((uint32_t)(r * 128 + cc * 16));
            size_t g = (size_t)(m0 + r) * GK + k0 + cc * 8;
            cp16(st + o,         (const void*)(Ah + g));
            cp16(st + 16384 + o, (const void*)(Al + g));
        }
        #pragma unroll
        for (int t = 0; t < 2; t++) {                 // B: [64 k][128 n], 256B rows
            int j = tid + t * 512;
            int r = j >> 4, cc = j & 15;
            uint32_t o = swz256((uint32_t)(r * 256 + cc * 16));
            size_t g = (size_t)(k0 + r) * N + n0 + cc * 8;
            cp16(st + 32768 + o, (const void*)(Bh + g));
            cp16(st + 49152 + o, (const void*)(Bl + g));
        }
        CP_COMMIT();
    };

    float acc[2][4][4];
    #pragma unroll
    for (int mf = 0; mf < 2; mf++)
        #pragma unroll
        for (int nf = 0; nf < 4; nf++)
            { acc[mf][nf][0]=0.f; acc[mf][nf][1]=0.f; acc[mf][nf][2]=0.f; acc[mf][nf][3]=0.f; }

    loadChunk(0, 0);
    loadChunk(1, 1);

    const int NC = GK / 64;
    int stg = 0;
    for (int c = 0; c < NC; c++) {
        int nst = stg + 2; if (nst >= 3) nst -= 3;
        if (c + 2 < NC) {
            loadChunk(c + 2, nst);                       // issue BEFORE wait
            asm volatile("cp.async.wait_group 2;\n");    // chunk c landed
        } else if (c + 1 < NC) {
            asm volatile("cp.async.wait_group 1;\n");
        } else {
            asm volatile("cp.async.wait_group 0;\n");
        }
        __syncthreads();

        const uint32_t st = sb + (uint32_t)stg * 65536;
        #pragma unroll
        for (int ks = 0; ks < 4; ks++) {
            uint32_t ah[2][4], alr[2][4];
            #pragma unroll
            for (int mf = 0; mf < 2; mf++) {
                uint32_t adr = st + swz128((uint32_t)(
                    (wm + mf * 16 + (l & 15)) * 128 + ks * 32 + ((l & 16) ? 16 : 0)));
                LDSM_X4(ah[mf], adr);
                LDSM_X4(alr[mf], adr + 16384);
            }
            #pragma unroll
            for (int g = 0; g < 2; g++) {
                uint32_t br = (uint32_t)(ks * 16 + (l & 7) + ((l & 8) ? 8 : 0));
                uint32_t bc = (uint32_t)((wn + g * 16) * 2 + ((l & 16) ? 16 : 0));
                uint32_t badr = st + 32768 + swz256(br * 256 + bc);
                uint32_t bh[4], bl[4];
                LDSM_X4T(bh, badr);
                LDSM_X4T(bl, badr + 16384);
                #pragma unroll
                for (int mf = 0; mf < 2; mf++) {
                    MMA4(acc[mf][2*g],   ah[mf],  bh[0], bh[1]);
                    MMA4(acc[mf][2*g+1], ah[mf],  bh[2], bh[3]);
                    MMA4(acc[mf][2*g],   ah[mf],  bl[0], bl[1]);
                    MMA4(acc[mf][2*g+1], ah[mf],  bl[2], bl[3]);
                    MMA4(acc[mf][2*g],   alr[mf], bh[0], bh[1]);
                    MMA4(acc[mf][2*g+1], alr[mf], bh[2], bh[3]);
                }
            }
        }
        __syncthreads();                                 // stage may be overwritten next iter
        if (++stg >= 3) stg -= 3;
    }

    // epilogue
    #pragma unroll
    for (int mf = 0; mf < 2; mf++) {
        int r0 = m0 + wm + mf * 16 + (l >> 2);
        #pragma unroll
        for (int nf = 0; nf < 4; nf++) {
            int cc = n0 + wn + nf * 8 + (l & 3) * 2;
            if (Cf) {
                *(float2*)(Cf + (size_t)r0 * N + cc) =
                    make_float2(acc[mf][nf][0], acc[mf][nf][1]);
                *(float2*)(Cf + (size_t)(r0 + 8) * N + cc) =
                    make_float2(acc[mf][nf][2], acc[mf][nf][3]);
            } else {
                uint32_t hi, lo;
                pk2(acc[mf][nf][0], acc[mf][nf][1], hi, lo);
                *(uint32_t*)(Oh + (size_t)r0 * N + cc) = hi;
                *(uint32_t*)(Ol + (size_t)r0 * N + cc) = lo;
                pk2(acc[mf][nf][2], acc[mf][nf][3], hi, lo);
                *(uint32_t*)(Oh + (size_t)(r0 + 8) * N + cc) = hi;
                *(uint32_t*)(Ol + (size_t)(r0 + 8) * N + cc) = lo;
            }
        }
    }
}

// ---------------------------------------------------------------------------
// conversions (float4-vectorized) & RoPE
// ---------------------------------------------------------------------------
__global__ void cvt_hl(const float* __restrict__ X,
                       __nv_bfloat16* __restrict__ H, __nv_bfloat16* __restrict__ L, int n4)
{
    int i = blockIdx.x * 256 + threadIdx.x;
    if (i >= n4) return;
    float4 v = *(const float4*)(X + (size_t)i * 4);
    uint32_t h01, l01, h23, l23;
    pk2(v.x, v.y, h01, l01);
    pk2(v.z, v.w, h23, l23);
    *(uint2*)(H + (size_t)i * 4) = make_uint2(h01, h23);
    *(uint2*)(L + (size_t)i * 4) = make_uint2(l01, l23);
}

__global__ void rope_table_k()
{
    int idx = blockIdx.x * blockDim.x + threadIdx.x;
    if (idx >= SS * 64) return;
    int pos = idx >> 6;
    int i   = idx & 63;
    float invf = (float)pow(10000.0, -((double)i) / 64.0);
    float angf = (float)pos * invf;
    double ang = (double)angf;
    g_cos[idx] = (float)cos(ang);
    g_sin[idx] = (float)sin(ang);
}

__global__ void rope_split_k(const float* __restrict__ X,
                             __nv_bfloat16* __restrict__ H,
                             __nv_bfloat16* __restrict__ L,
                             int nh, float scale)
{
    int idx = blockIdx.x * blockDim.x + threadIdx.x;
    int total = MR * nh * 64;
    if (idx >= total) return;
    int half = idx & 63;
    int h    = (idx >> 6) % nh;
    int r    = idx / (64 * nh);
    int s    = r % SS;
    size_t base = (size_t)r * nh * HD + (size_t)h * HD;
    float c  = g_cos[s * 64 + half];
    float sn = g_sin[s * 64 + half];
    float x1 = X[base + half];
    float x2 = X[base + half + 64];
    float y1 = (x1 * c - x2 * sn) * scale;
    float y2 = (x2 * c + x1 * sn) * scale;
    __nv_bfloat16 h1 = __float2bfloat16(y1);
    __nv_bfloat16 h2 = __float2bfloat16(y2);
    H[base + half]      = h1;
    H[base + half + 64] = h2;
    L[base + half]      = __float2bfloat16(y1 - __bfloat162float(h1));
    L[base + half + 64] = __float2bfloat16(y2 - __bfloat162float(h2));
}

// ---------------------------------------------------------------------------
// FlashAttention-2 mma.sync bf16 split (proven R7 kernel, unchanged).
// ---------------------------------------------------------------------------
#define ATT_SMEM 196608

__global__ void __launch_bounds__(256) attn_mma()
{
    extern __shared__ __align__(1024) char smdyn[];
    const int qb = blockIdx.x, h = blockIdx.y, b = blockIdx.z;
    const int kvh = h / GRP;
    const int tid = threadIdx.x, w = tid >> 5, l = tid & 31;
    const uint32_t sb = su32(smdyn);
    const uint32_t Qh_s = sb;
    const uint32_t KV0  = sb + 65536;

    {
        const __nv_bfloat16* qh = g_Qh + (size_t)(b * SS + qb * 128) * HID + h * HD;
        const __nv_bfloat16* ql = g_Ql + (size_t)(b * SS + qb * 128) * HID + h * HD;
        #pragma unroll
        for (int t = 0; t < 8; t++) {
            int j = tid + t * 256;
            int r = j >> 4, c = j & 15;
            uint32_t o = swz256((uint32_t)(r * 256 + c * 16));
            cp16(Qh_s + o,         (const void*)(qh + (size_t)r * HID + c * 8));
            cp16(Qh_s + 32768 + o, (const void*)(ql + (size_t)r * HID + c * 8));
        }
        CP_COMMIT();
    }

    const int NT = 2 * qb + 2;
    auto loadKV = [&](int kt) {
        const uint32_t st = KV0 + (uint32_t)(kt & 1) * 65536;
        const size_t rb = (size_t)(b * SS + kt * 64) * KVD + kvh * HD;
        #pragma unroll
        for (int t = 0; t < 4; t++) {
            int j = tid + t * 256;
            int r = j >> 4, c = j & 15;
            uint32_t o = swz256((uint32_t)(r * 256 + c * 16));
            size_t g = rb + (size_t)r * KVD + c * 8;
            cp16(st +         o, (const void*)(g_Kh + g));
            cp16(st + 16384 + o, (const void*)(g_Kl + g));
            cp16(st + 32768 + o, (const void*)(g_Vh + g));
            cp16(st + 49152 + o, (const void*)(g_Vl + g));
        }
        CP_COMMIT();
    };
    loadKV(0);

    const int m0 = w * 16;
    const int qg0 = qb * 128 + m0 + (l >> 2);
    float O[16][4];
    #pragma unroll
    for (int f = 0; f < 16; f++)
        { O[f][0] = 0.f; O[f][1] = 0.f; O[f][2] = 0.f; O[f][3] = 0.f; }
    float mr0 = -1e30f, mr1 = -1e30f, sl0 = 0.f, sl1 = 0.f;

    for (int kt = 0; kt < NT; kt++) {
        if (kt + 1 < NT) {
            loadKV(kt + 1);
            asm volatile("cp.async.wait_group 1;\n");
        } else {
            asm volatile("cp.async.wait_group 0;\n");
        }
        __syncthreads();

        const uint32_t st = KV0 + (uint32_t)(kt & 1) * 65536;

        float s[8][4];
        #pragma unroll
        for (int nb = 0; nb < 8; nb++)
            { s[nb][0] = 0.f; s[nb][1] = 0.f; s[nb][2] = 0.f; s[nb][3] = 0.f; }

        #pragma unroll
        for (int ks = 0; ks < 8; ks++) {
            uint32_t aQh[4], aQl[4];
            uint32_t aaddr = Qh_s + swz256(
                (uint32_t)((m0 + (l & 15)) * 256 + ks * 32 + ((l & 16) ? 16 : 0)));
            LDSM_X4(aQh, aaddr);
            LDSM_X4(aQl, aaddr + 32768);
            #pragma unroll
            for (int nb2 = 0; nb2 < 4; nb2++) {
                uint32_t brow = (uint32_t)(nb2 * 16 + (l & 7) + ((l & 16) ? 8 : 0));
                uint32_t baddr = st + swz256(brow * 256 + ks * 32 + ((l & 8) ? 16 : 0));
                uint32_t bh[4], bl[4];
                LDSM_X4(bh, baddr);
                LDSM_X4(bl, baddr + 16384);
                MMA4(s[2*nb2],   aQh, bh[0], bh[1]);
                MMA4(s[2*nb2+1], aQh, bh[2], bh[3]);
                MMA4(s[2*nb2],   aQh, bl[0], bl[1]);
                MMA4(s[2*nb2+1], aQh, bl[2], bl[3]);
                MMA4(s[2*nb2],   aQl, bh[0], bh[1]);
                MMA4(s[2*nb2+1], aQl, bh[2], bh[3]);
            }
        }

        const int kgb = kt * 64 + (l & 3) * 2;
        float mx0 = -1e30f, mx1 = -1e30f;
        #pragma unroll
        for (int nb = 0; nb < 8; nb++) {
            int kg = kgb + nb * 8;
            if (kg     > qg0)     s[nb][0] = -1e30f;
            if (kg + 1 > qg0)     s[nb][1] = -1e30f;
            if (kg     > qg0 + 8) s[nb][2] = -1e30f;
            if (kg + 1 > qg0 + 8) s[nb][3] = -1e30f;
            mx0 = fmaxf(mx0, fmaxf(s[nb][0], s[nb][1]));
            mx1 = fmaxf(mx1, fmaxf(s[nb][2], s[nb][3]));
        }
        mx0 = fmaxf(mx0, __shfl_xor_sync(0xffffffffu, mx0, 1));
        mx0 = fmaxf(mx0, __shfl_xor_sync(0xffffffffu, mx0, 2));
        mx1 = fmaxf(mx1, __shfl_xor_sync(0xffffffffu, mx1, 1));
        mx1 = fmaxf(mx1, __shfl_xor_sync(0xffffffffu, mx1, 2));

        float mn0 = fmaxf(mr0, mx0), mn1 = fmaxf(mr1, mx1);
        float al0 = __expf(mr0 - mn0), al1 = __expf(mr1 - mn1);
        mr0 = mn0; mr1 = mn1;
        float sum0 = 0.f, sum1 = 0.f;
        #pragma unroll
        for (int nb = 0; nb < 8; nb++) {
            s[nb][0] = __expf(s[nb][0] - mn0);
            s[nb][1] = __expf(s[nb][1] - mn0);
            s[nb][2] = __expf(s[nb][2] - mn1);
            s[nb][3] = __expf(s[nb][3] - mn1);
            sum0 += s[nb][0] + s[nb][1];
            sum1 += s[nb][2] + s[nb][3];
        }
        sum0 += __shfl_xor_sync(0xffffffffu, sum0, 1);
        sum0 += __shfl_xor_sync(0xffffffffu, sum0, 2);
        sum1 += __shfl_xor_sync(0xffffffffu, sum1, 1);
        sum1 += __shfl_xor_sync(0xffffffffu, sum1, 2);
        sl0 = sl0 * al0 + sum0;
        sl1 = sl1 * al1 + sum1;
        #pragma unroll
        for (int f = 0; f < 16; f++) {
            O[f][0] *= al0; O[f][1] *= al0; O[f][2] *= al1; O[f][3] *= al1;
        }

        #pragma unroll
        for (int j = 0; j < 4; j++) {
            uint32_t ph[4], pl[4];
            pk2(s[2*j][0],   s[2*j][1],   ph[0], pl[0]);
            pk2(s[2*j][2],   s[2*j][3],   ph[1], pl[1]);
            pk2(s[2*j+1][0], s[2*j+1][1], ph[2], pl[2]);
            pk2(s[2*j+1][2], s[2*j+1][3], ph[3], pl[3]);
            uint32_t vrow = (uint32_t)(j * 16 + (l & 7) + ((l & 8) ? 8 : 0));
            #pragma unroll
            for (int nb2 = 0; nb2 < 8; nb2++) {
                uint32_t vaddr = st + 32768 +
                    swz256(vrow * 256 + nb2 * 32 + ((l & 16) ? 16 : 0));
                uint32_t vh[4], vl[4];
                LDSM_X4T(vh, vaddr);
                LDSM_X4T(vl, vaddr + 16384);
                MMA4(O[2*nb2],   ph, vh[0], vh[1]);
                MMA4(O[2*nb2+1], ph, vh[2], vh[3]);
                MMA4(O[2*nb2],   ph, vl[0], vl[1]);
                MMA4(O[2*nb2+1], ph, vl[2], vl[3]);
                MMA4(O[2*nb2],   pl, vh[0], vh[1]);
                MMA4(O[2*nb2+1], pl, vh[2], vh[3]);
            }
        }
        __syncthreads();
    }

    const float i0 = 1.0f / sl0, i1 = 1.0f / sl1;
    size_t base0 = (size_t)(b * SS + qg0) * HID + (size_t)h * HD;
    size_t base1 = base0 + (size_t)8 * HID;
    #pragma unroll
    for (int nb = 0; nb < 16; nb++) {
        int col = nb * 8 + (l & 3) * 2;
        uint32_t hi, lo;
        pk2(O[nb][0] * i0, O[nb][1] * i0, hi, lo);
        *(uint32_t*)(g_Ath + base0 + col) = hi;
        *(uint32_t*)(g_Atl + base0 + col) = lo;
        pk2(O[nb][2] * i1, O[nb][3] * i1, hi, lo);
        *(uint32_t*)(g_Ath + base1 + col) = hi;
        *(uint32_t*)(g_Atl + base1 + col) = lo;
    }
}

// ---------------------------------------------------------------------------
extern "C" void kernel_launch(void* const* d_in, const int* in_sizes, int n_in,
                              void* d_out, int out_size)
{
    (void)in_sizes; (void)n_in; (void)out_size;
    const float* x  = (const float*)d_in[0];
    const float* Wq = (const float*)d_in[1];
    const float* Wk = (const float*)d_in[2];
    const float* Wv = (const float*)d_in[3];
    const float* Wo = (const float*)d_in[4];
    float* out = (float*)d_out;

    float *Qp, *Kp;
    __nv_bfloat16 *xh, *xl, *wqh, *wql, *wkh, *wkl, *wvh, *wvl, *woh, *wol;
    __nv_bfloat16 *qh, *ql, *kh, *kl, *vh, *vl, *ath, *atl;
    cudaGetSymbolAddress((void**)&Qp, g_Q);
    cudaGetSymbolAddress((void**)&Kp, g_K);
    cudaGetSymbolAddress((void**)&xh, g_xh);   cudaGetSymbolAddress((void**)&xl, g_xl);
    cudaGetSymbolAddress((void**)&wqh, g_Wqh); cudaGetSymbolAddress((void**)&wql, g_Wql);
    cudaGetSymbolAddress((void**)&wkh, g_Wkh); cudaGetSymbolAddress((void**)&wkl, g_Wkl);
    cudaGetSymbolAddress((void**)&wvh, g_Wvh); cudaGetSymbolAddress((void**)&wvl, g_Wvl);
    cudaGetSymbolAddress((void**)&woh, g_Woh); cudaGetSymbolAddress((void**)&wol, g_Wol);
    cudaGetSymbolAddress((void**)&qh, g_Qh);   cudaGetSymbolAddress((void**)&ql, g_Ql);
    cudaGetSymbolAddress((void**)&kh, g_Kh);   cudaGetSymbolAddress((void**)&kl, g_Kl);
    cudaGetSymbolAddress((void**)&vh, g_Vh);   cudaGetSymbolAddress((void**)&vl, g_Vl);
    cudaGetSymbolAddress((void**)&ath, g_Ath); cudaGetSymbolAddress((void**)&atl, g_Atl);

    cudaFuncSetAttribute(gemm_bf16s, cudaFuncAttributeMaxDynamicSharedMemorySize, GEMM_SMEM);
    cudaFuncSetAttribute(attn_mma, cudaFuncAttributeMaxDynamicSharedMemorySize, ATT_SMEM);

    cvt_hl<<<(MR * HID / 4 + 255) / 256, 256>>>(x,  xh,  xl,  MR * HID / 4);
    cvt_hl<<<(HID * HID / 4 + 255) / 256, 256>>>(Wq, wqh, wql, HID * HID / 4);
    cvt_hl<<<(HID * KVD / 4 + 255) / 256, 256>>>(Wk, wkh, wkl, HID * KVD / 4);
    cvt_hl<<<(HID * KVD / 4 + 255) / 256, 256>>>(Wv, wvh, wvl, HID * KVD / 4);
    cvt_hl<<<(HID * HID / 4 + 255) / 256, 256>>>(Wo, woh, wol, HID * HID / 4);

    gemm_bf16s<<<dim3(HID / 128, MR / 128), 512, GEMM_SMEM>>>(
        xh, xl, wqh, wql, Qp, nullptr, nullptr, HID);
    gemm_bf16s<<<dim3(KVD / 128, MR / 128), 512, GEMM_SMEM>>>(
        xh, xl, wkh, wkl, Kp, nullptr, nullptr, KVD);
    gemm_bf16s<<<dim3(KVD / 128, MR / 128), 512, GEMM_SMEM>>>(
        xh, xl, wvh, wvl, nullptr, vh, vl, KVD);

    rope_table_k<<<(SS * 64 + 255) / 256, 256>>>();
    const float scale = 0.08838834764831845f;   // 1/sqrt(128)
    rope_split_k<<<(MR * NHQ  * 64 + 255) / 256, 256>>>(Qp, qh, ql, NHQ, scale);
    rope_split_k<<<(MR * NHKV * 64 + 255) / 256, 256>>>(Kp, kh, kl, NHKV, 1.0f);

    attn_mma<<<dim3(SS / 128, NHQ, BB), 256, ATT_SMEM>>>();

    gemm_bf16s<<<dim3(HID / 128, MR / 128), 512, GEMM_SMEM>>>(
        ath, atl, woh, wol, out, nullptr, nullptr, HID);
}

// round 15
// speedup vs baseline: 1.0266x; 1.0266x over previous
#include <cuda_runtime.h>
#include <cuda_bf16.h>
#include <math.h>
#include <stdint.h>

#define BB 2
#define SS 2048
#define HID 4096
#define NHQ 32
#define NHKV 8
#define HD 128
#define MR (BB*SS)          // 4096 rows
#define KVD (NHKV*HD)       // 1024
#define GRP (NHQ/NHKV)      // 4
#define GK 4096             // all GEMMs have K=4096
#define NQKV (HID + 2*KVD)  // 6144 fused projection width

// ---------------- scratch (__device__ globals) ------------------------------
__device__ float g_cos[SS*(HD/2)];
__device__ float g_sin[SS*(HD/2)];
__device__ __nv_bfloat16 g_xh[MR*HID],  g_xl[MR*HID];
__device__ __nv_bfloat16 g_Wh[GK*NQKV], g_Wl[GK*NQKV];     // [K, Nq|Nk|Nv]
__device__ __nv_bfloat16 g_Woh[HID*HID], g_Wol[HID*HID];
__device__ __nv_bfloat16 g_Qh[MR*HID], g_Ql[MR*HID];
__device__ __nv_bfloat16 g_Kh[MR*KVD], g_Kl[MR*KVD];
__device__ __nv_bfloat16 g_Vh[MR*KVD], g_Vl[MR*KVD];
__device__ __nv_bfloat16 g_Ath[MR*HID], g_Atl[MR*HID];

// ---------------- PTX helpers (portable sm_80-era ops) ----------------------
__device__ __forceinline__ uint32_t su32(const void* p) {
    uint32_t a;
    asm("{ .reg .u64 t; cvta.to.shared.u64 t, %1; cvt.u32.u64 %0, t; }"
        : "=r"(a) : "l"(p));
    return a;
}
__device__ __forceinline__ void cp16(uint32_t sa, const void* g) {
    asm volatile("cp.async.cg.shared.global [%0], [%1], 16;\n" :: "r"(sa), "l"(g));
}
#define CP_COMMIT() asm volatile("cp.async.commit_group;\n")
#define LDSM_X4(r, a) \
    asm volatile("ldmatrix.sync.aligned.m8n8.x4.shared.b16 {%0,%1,%2,%3}, [%4];" \
        : "=r"((r)[0]), "=r"((r)[1]), "=r"((r)[2]), "=r"((r)[3]) : "r"(a))
#define LDSM_X4T(r, a) \
    asm volatile("ldmatrix.sync.aligned.m8n8.x4.trans.shared.b16 {%0,%1,%2,%3}, [%4];" \
        : "=r"((r)[0]), "=r"((r)[1]), "=r"((r)[2]), "=r"((r)[3]) : "r"(a))
#define MMA4(d, a, b0, b1) \
    asm volatile("mma.sync.aligned.m16n8k16.row.col.f32.bf16.bf16.f32 " \
        "{%0,%1,%2,%3},{%4,%5,%6,%7},{%8,%9},{%0,%1,%2,%3};" \
        : "+f"((d)[0]), "+f"((d)[1]), "+f"((d)[2]), "+f"((d)[3]) \
        : "r"((a)[0]), "r"((a)[1]), "r"((a)[2]), "r"((a)[3]), "r"(b0), "r"(b1))

__device__ __forceinline__ uint32_t swz256(uint32_t o) {   // 256B rows
    return o ^ (((o >> 8) & 7u) << 4);
}
__device__ __forceinline__ uint32_t swz128(uint32_t o) {   // 128B rows
    return o ^ (((o >> 7) & 7u) << 4);
}
__device__ __forceinline__ void pk2(float x, float y, uint32_t& hi, uint32_t& lo) {
    __nv_bfloat16 hx = __float2bfloat16(x), hy = __float2bfloat16(y);
    hi = ((uint32_t)*(uint16_t*)&hy << 16) | *(uint16_t*)&hx;
    __nv_bfloat16 lx = __float2bfloat16(x - __bfloat162float(hx));
    __nv_bfloat16 ly = __float2bfloat16(y - __bfloat162float(hy));
    lo = ((uint32_t)*(uint16_t*)&ly << 16) | *(uint16_t*)&lx;
}

// ---------------------------------------------------------------------------
// Split-bf16 tensor-core GEMM (R13 mainloop): C = A[M,4096] @ B[4096,N]
// MODE 0: fp32 store to Cf.   MODE 1: fused RoPE+scale+split QKV epilogue.
// CTA 128x128, BK=64, 3-stage, 256 threads, 8 warps of 64x32.
// ---------------------------------------------------------------------------
#define GEMM_SMEM 196608
#define EPIT 130                 // epilogue smem pitch (floats)

template<int MODE>
__global__ void __launch_bounds__(256) gemm_bf16s(
    const __nv_bfloat16* __restrict__ Ah, const __nv_bfloat16* __restrict__ Al,
    const __nv_bfloat16* __restrict__ Bh, const __nv_bfloat16* __restrict__ Bl,
    float* __restrict__ Cf, int N)
{
    extern __shared__ __align__(1024) char smg[];
    const uint32_t sb = su32(smg);
    const int tid = threadIdx.x, w = tid >> 5, l = tid & 31;
    const int n0 = blockIdx.x * 128, m0 = blockIdx.y * 128;
    const int wm = (w & 1) * 64, wn = (w >> 1) * 32;

    auto loadChunk = [&](int c, int stg) {
        const uint32_t st = sb + (uint32_t)stg * 65536;
        const int k0 = c * 64;
        #pragma unroll
        for (int t = 0; t < 4; t++) {                 // A: [128 m][64 k], 128B rows
            int j = tid + t * 256;
            int r = j >> 3, cc = j & 7;
            uint32_t o = swz128((uint32_t)(r * 128 + cc * 16));
            size_t g = (size_t)(m0 + r) * GK + k0 + cc * 8;
            cp16(st + o,         (const void*)(Ah + g));
            cp16(st + 16384 + o, (const void*)(Al + g));
        }
        #pragma unroll
        for (int t = 0; t < 4; t++) {                 // B: [64 k][128 n], 256B rows
            int j = tid + t * 256;
            int r = j >> 4, cc = j & 15;
            uint32_t o = swz256((uint32_t)(r * 256 + cc * 16));
            size_t g = (size_t)(k0 + r) * N + n0 + cc * 8;
            cp16(st + 32768 + o, (const void*)(Bh + g));
            cp16(st + 49152 + o, (const void*)(Bl + g));
        }
        CP_COMMIT();
    };

    float acc[4][4][4];
    #pragma unroll
    for (int mf = 0; mf < 4; mf++)
        #pragma unroll
        for (int nf = 0; nf < 4; nf++)
            { acc[mf][nf][0]=0.f; acc[mf][nf][1]=0.f; acc[mf][nf][2]=0.f; acc[mf][nf][3]=0.f; }

    loadChunk(0, 0);
    loadChunk(1, 1);

    const int NC = GK / 64;
    int stg = 0;
    for (int c = 0; c < NC; c++) {
        if (c + 1 < NC) {
            asm volatile("cp.async.wait_group 1;\n");
        } else {
            asm volatile("cp.async.wait_group 0;\n");
        }
        __syncthreads();
        int nstg = stg + 2; if (nstg >= 3) nstg -= 3;
        if (c + 2 < NC) loadChunk(c + 2, nstg);

        const uint32_t st = sb + (uint32_t)stg * 65536;
        #pragma unroll
        for (int ks = 0; ks < 4; ks++) {
            uint32_t ah[4][4], alr[4][4];
            #pragma unroll
            for (int mf = 0; mf < 4; mf++) {
                uint32_t adr = st + swz128((uint32_t)(
                    (wm + mf * 16 + (l & 15)) * 128 + ks * 32 + ((l & 16) ? 16 : 0)));
                LDSM_X4(ah[mf], adr);
                LDSM_X4(alr[mf], adr + 16384);
            }
            #pragma unroll
            for (int g = 0; g < 2; g++) {
                uint32_t br = (uint32_t)(ks * 16 + (l & 7) + ((l & 8) ? 8 : 0));
                uint32_t bc = (uint32_t)((wn + g * 16) * 2 + ((l & 16) ? 16 : 0));
                uint32_t badr = st + 32768 + swz256(br * 256 + bc);
                uint32_t bh[4], bl[4];
                LDSM_X4T(bh, badr);
                LDSM_X4T(bl, badr + 16384);
                #pragma unroll
                for (int mf = 0; mf < 4; mf++) {
                    MMA4(acc[mf][2*g],   ah[mf],  bh[0], bh[1]);
                    MMA4(acc[mf][2*g+1], ah[mf],  bh[2], bh[3]);
                    MMA4(acc[mf][2*g],   ah[mf],  bl[0], bl[1]);
                    MMA4(acc[mf][2*g+1], ah[mf],  bl[2], bl[3]);
                    MMA4(acc[mf][2*g],   alr[mf], bh[0], bh[1]);
                    MMA4(acc[mf][2*g+1], alr[mf], bh[2], bh[3]);
                }
            }
        }
        if (++stg >= 3) stg -= 3;
    }

    if (MODE == 0) {
        // plain fp32 epilogue
        #pragma unroll
        for (int mf = 0; mf < 4; mf++) {
            int r0 = m0 + wm + mf * 16 + (l >> 2);
            #pragma unroll
            for (int nf = 0; nf < 4; nf++) {
                int cc = n0 + wn + nf * 8 + (l & 3) * 2;
                *(float2*)(Cf + (size_t)r0 * N + cc) =
                    make_float2(acc[mf][nf][0], acc[mf][nf][1]);
                *(float2*)(Cf + (size_t)(r0 + 8) * N + cc) =
                    make_float2(acc[mf][nf][2], acc[mf][nf][3]);
            }
        }
    } else {
        // fused RoPE + scale + split epilogue via smem exchange
        __syncthreads();                 // all warps done reading stage smem
        float* sm = (float*)smg;
        #pragma unroll
        for (int mf = 0; mf < 4; mf++) {
            int r0 = wm + mf * 16 + (l >> 2);
            #pragma unroll
            for (int nf = 0; nf < 4; nf++) {
                int cc = wn + nf * 8 + (l & 3) * 2;
                *(float2*)(sm + r0 * EPIT + cc) =
                    make_float2(acc[mf][nf][0], acc[mf][nf][1]);
                *(float2*)(sm + (r0 + 8) * EPIT + cc) =
                    make_float2(acc[mf][nf][2], acc[mf][nf][3]);
            }
        }
        __syncthreads();

        // routing: Q [0,HID), K [HID,HID+KVD), V rest
        __nv_bfloat16 *H, *L;
        int stride, colb;
        bool rope;
        float scale;
        if (n0 < HID)            { H = g_Qh; L = g_Ql; stride = HID; colb = n0;
                                   rope = true;  scale = 0.08838834764831845f; }
        else if (n0 < HID + KVD) { H = g_Kh; L = g_Kl; stride = KVD; colb = n0 - HID;
                                   rope = true;  scale = 1.0f; }
        else                     { H = g_Vh; L = g_Vl; stride = KVD; colb = n0 - HID - KVD;
                                   rope = false; scale = 1.0f; }

        #pragma unroll 4
        for (int i = 0; i < 32; i++) {
            int idx = tid + i * 256;           // 128 rows x 64 halves
            int r = idx >> 6, half = idx & 63;
            float x1 = sm[r * EPIT + half];
            float x2 = sm[r * EPIT + half + 64];
            float cth = 1.f, sth = 0.f;
            int grow = m0 + r;
            if (rope) {
                int s = grow & (SS - 1);
                cth = g_cos[s * 64 + half];
                sth = g_sin[s * 64 + half];
            }
            float y1 = (x1 * cth - x2 * sth) * scale;
            float y2 = (x2 * cth + x1 * sth) * scale;
            __nv_bfloat16 h1 = __float2bfloat16(y1);
            __nv_bfloat16 h2 = __float2bfloat16(y2);
            size_t o = (size_t)grow * stride + colb + half;
            H[o]      = h1;
            H[o + 64] = h2;
            L[o]      = __float2bfloat16(y1 - __bfloat162float(h1));
            L[o + 64] = __float2bfloat16(y2 - __bfloat162float(h2));
        }
    }
}

// ---------------------------------------------------------------------------
// conversions & RoPE table
// ---------------------------------------------------------------------------
__global__ void cvt_hl(const float* __restrict__ X,
                       __nv_bfloat16* __restrict__ H, __nv_bfloat16* __restrict__ L, int n4)
{
    int i = blockIdx.x * 256 + threadIdx.x;
    if (i >= n4) return;
    float4 v = *(const float4*)(X + (size_t)i * 4);
    uint32_t h01, l01, h23, l23;
    pk2(v.x, v.y, h01, l01);
    pk2(v.z, v.w, h23, l23);
    *(uint2*)(H + (size_t)i * 4) = make_uint2(h01, h23);
    *(uint2*)(L + (size_t)i * 4) = make_uint2(l01, l23);
}

// concat Wq|Wk|Wv (all [K, n]) into [K, 6144] split limbs
__global__ void cvt_qkv(const float* __restrict__ Wq, const float* __restrict__ Wk,
                        const float* __restrict__ Wv)
{
    int i = blockIdx.x * 256 + threadIdx.x;          // one per 4 cols
    if (i >= GK * (NQKV / 4)) return;
    int k = i / (NQKV / 4);
    int n = (i - k * (NQKV / 4)) * 4;
    const float* src;
    if (n < HID)            src = Wq + (size_t)k * HID + n;
    else if (n < HID + KVD) src = Wk + (size_t)k * KVD + (n - HID);
    else                    src = Wv + (size_t)k * KVD + (n - HID - KVD);
    float4 v = *(const float4*)src;
    uint32_t h01, l01, h23, l23;
    pk2(v.x, v.y, h01, l01);
    pk2(v.z, v.w, h23, l23);
    size_t o = (size_t)k * NQKV + n;
    *(uint2*)(g_Wh + o) = make_uint2(h01, h23);
    *(uint2*)(g_Wl + o) = make_uint2(l01, l23);
}

__global__ void rope_table_k()
{
    int idx = blockIdx.x * blockDim.x + threadIdx.x;
    if (idx >= SS * 64) return;
    int pos = idx >> 6;
    int i   = idx & 63;
    float invf = (float)pow(10000.0, -((double)i) / 64.0);
    float angf = (float)pos * invf;
    double ang = (double)angf;
    g_cos[idx] = (float)cos(ang);
    g_sin[idx] = (float)sin(ang);
}

// ---------------------------------------------------------------------------
// FlashAttention-2 mma.sync bf16 split (proven R7 kernel; qb reversed so the
// largest-work CTAs launch first).
// ---------------------------------------------------------------------------
#define ATT_SMEM 196608

__global__ void __launch_bounds__(256) attn_mma()
{
    extern __shared__ __align__(1024) char smdyn[];
    const int qb = (int)gridDim.x - 1 - (int)blockIdx.x;   // largest first
    const int h = blockIdx.y, b = blockIdx.z;
    const int kvh = h / GRP;
    const int tid = threadIdx.x, w = tid >> 5, l = tid & 31;
    const uint32_t sb = su32(smdyn);
    const uint32_t Qh_s = sb;
    const uint32_t KV0  = sb + 65536;

    {
        const __nv_bfloat16* qh = g_Qh + (size_t)(b * SS + qb * 128) * HID + h * HD;
        const __nv_bfloat16* ql = g_Ql + (size_t)(b * SS + qb * 128) * HID + h * HD;
        #pragma unroll
        for (int t = 0; t < 8; t++) {
            int j = tid + t * 256;
            int r = j >> 4, c = j & 15;
            uint32_t o = swz256((uint32_t)(r * 256 + c * 16));
            cp16(Qh_s + o,         (const void*)(qh + (size_t)r * HID + c * 8));
            cp16(Qh_s + 32768 + o, (const void*)(ql + (size_t)r * HID + c * 8));
        }
        CP_COMMIT();
    }

    const int NT = 2 * qb + 2;
    auto loadKV = [&](int kt) {
        const uint32_t st = KV0 + (uint32_t)(kt & 1) * 65536;
        const size_t rb = (size_t)(b * SS + kt * 64) * KVD + kvh * HD;
        #pragma unroll
        for (int t = 0; t < 4; t++) {
            int j = tid + t * 256;
            int r = j >> 4, c = j & 15;
            uint32_t o = swz256((uint32_t)(r * 256 + c * 16));
            size_t g = rb + (size_t)r * KVD + c * 8;
            cp16(st +         o, (const void*)(g_Kh + g));
            cp16(st + 16384 + o, (const void*)(g_Kl + g));
            cp16(st + 32768 + o, (const void*)(g_Vh + g));
            cp16(st + 49152 + o, (const void*)(g_Vl + g));
        }
        CP_COMMIT();
    };
    loadKV(0);

    const int m0 = w * 16;
    const int qg0 = qb * 128 + m0 + (l >> 2);
    float O[16][4];
    #pragma unroll
    for (int f = 0; f < 16; f++)
        { O[f][0] = 0.f; O[f][1] = 0.f; O[f][2] = 0.f; O[f][3] = 0.f; }
    float mr0 = -1e30f, mr1 = -1e30f, sl0 = 0.f, sl1 = 0.f;

    for (int kt = 0; kt < NT; kt++) {
        if (kt + 1 < NT) {
            loadKV(kt + 1);
            asm volatile("cp.async.wait_group 1;\n");
        } else {
            asm volatile("cp.async.wait_group 0;\n");
        }
        __syncthreads();

        const uint32_t st = KV0 + (uint32_t)(kt & 1) * 65536;

        float s[8][4];
        #pragma unroll
        for (int nb = 0; nb < 8; nb++)
            { s[nb][0] = 0.f; s[nb][1] = 0.f; s[nb][2] = 0.f; s[nb][3] = 0.f; }

        #pragma unroll
        for (int ks = 0; ks < 8; ks++) {
            uint32_t aQh[4], aQl[4];
            uint32_t aaddr = Qh_s + swz256(
                (uint32_t)((m0 + (l & 15)) * 256 + ks * 32 + ((l & 16) ? 16 : 0)));
            LDSM_X4(aQh, aaddr);
            LDSM_X4(aQl, aaddr + 32768);
            #pragma unroll
            for (int nb2 = 0; nb2 < 4; nb2++) {
                uint32_t brow = (uint32_t)(nb2 * 16 + (l & 7) + ((l & 16) ? 8 : 0));
                uint32_t baddr = st + swz256(brow * 256 + ks * 32 + ((l & 8) ? 16 : 0));
                uint32_t bh[4], bl[4];
                LDSM_X4(bh, baddr);
                LDSM_X4(bl, baddr + 16384);
                MMA4(s[2*nb2],   aQh, bh[0], bh[1]);
                MMA4(s[2*nb2+1], aQh, bh[2], bh[3]);
                MMA4(s[2*nb2],   aQh, bl[0], bl[1]);
                MMA4(s[2*nb2+1], aQh, bl[2], bl[3]);
                MMA4(s[2*nb2],   aQl, bh[0], bh[1]);
                MMA4(s[2*nb2+1], aQl, bh[2], bh[3]);
            }
        }

        const int kgb = kt * 64 + (l & 3) * 2;
        float mx0 = -1e30f, mx1 = -1e30f;
        #pragma unroll
        for (int nb = 0; nb < 8; nb++) {
            int kg = kgb + nb * 8;
            if (kg     > qg0)     s[nb][0] = -1e30f;
            if (kg + 1 > qg0)     s[nb][1] = -1e30f;
            if (kg     > qg0 + 8) s[nb][2] = -1e30f;
            if (kg + 1 > qg0 + 8) s[nb][3] = -1e30f;
            mx0 = fmaxf(mx0, fmaxf(s[nb][0], s[nb][1]));
            mx1 = fmaxf(mx1, fmaxf(s[nb][2], s[nb][3]));
        }
        mx0 = fmaxf(mx0, __shfl_xor_sync(0xffffffffu, mx0, 1));
        mx0 = fmaxf(mx0, __shfl_xor_sync(0xffffffffu, mx0, 2));
        mx1 = fmaxf(mx1, __shfl_xor_sync(0xffffffffu, mx1, 1));
        mx1 = fmaxf(mx1, __shfl_xor_sync(0xffffffffu, mx1, 2));

        float mn0 = fmaxf(mr0, mx0), mn1 = fmaxf(mr1, mx1);
        float al0 = __expf(mr0 - mn0), al1 = __expf(mr1 - mn1);
        mr0 = mn0; mr1 = mn1;
        float sum0 = 0.f, sum1 = 0.f;
        #pragma unroll
        for (int nb = 0; nb < 8; nb++) {
            s[nb][0] = __expf(s[nb][0] - mn0);
            s[nb][1] = __expf(s[nb][1] - mn0);
            s[nb][2] = __expf(s[nb][2] - mn1);
            s[nb][3] = __expf(s[nb][3] - mn1);
            sum0 += s[nb][0] + s[nb][1];
            sum1 += s[nb][2] + s[nb][3];
        }
        sum0 += __shfl_xor_sync(0xffffffffu, sum0, 1);
        sum0 += __shfl_xor_sync(0xffffffffu, sum0, 2);
        sum1 += __shfl_xor_sync(0xffffffffu, sum1, 1);
        sum1 += __shfl_xor_sync(0xffffffffu, sum1, 2);
        sl0 = sl0 * al0 + sum0;
        sl1 = sl1 * al1 + sum1;
        #pragma unroll
        for (int f = 0; f < 16; f++) {
            O[f][0] *= al0; O[f][1] *= al0; O[f][2] *= al1; O[f][3] *= al1;
        }

        #pragma unroll
        for (int j = 0; j < 4; j++) {
            uint32_t ph[4], pl[4];
            pk2(s[2*j][0],   s[2*j][1],   ph[0], pl[0]);
            pk2(s[2*j][2],   s[2*j][3],   ph[1], pl[1]);
            pk2(s[2*j+1][0], s[2*j+1][1], ph[2], pl[2]);
            pk2(s[2*j+1][2], s[2*j+1][3], ph[3], pl[3]);
            uint32_t vrow = (uint32_t)(j * 16 + (l & 7) + ((l & 8) ? 8 : 0));
            #pragma unroll
            for (int nb2 = 0; nb2 < 8; nb2++) {
                uint32_t vaddr = st + 32768 +
                    swz256(vrow * 256 + nb2 * 32 + ((l & 16) ? 16 : 0));
                uint32_t vh[4], vl[4];
                LDSM_X4T(vh, vaddr);
                LDSM_X4T(vl, vaddr + 16384);
                MMA4(O[2*nb2],   ph, vh[0], vh[1]);
                MMA4(O[2*nb2+1], ph, vh[2], vh[3]);
                MMA4(O[2*nb2],   ph, vl[0], vl[1]);
                MMA4(O[2*nb2+1], ph, vl[2], vl[3]);
                MMA4(O[2*nb2],   pl, vh[0], vh[1]);
                MMA4(O[2*nb2+1], pl, vh[2], vh[3]);
            }
        }
        __syncthreads();
    }

    const float i0 = 1.0f / sl0, i1 = 1.0f / sl1;
    size_t base0 = (size_t)(b * SS + qg0) * HID + (size_t)h * HD;
    size_t base1 = base0 + (size_t)8 * HID;
    #pragma unroll
    for (int nb = 0; nb < 16; nb++) {
        int col = nb * 8 + (l & 3) * 2;
        uint32_t hi, lo;
        pk2(O[nb][0] * i0, O[nb][1] * i0, hi, lo);
        *(uint32_t*)(g_Ath + base0 + col) = hi;
        *(uint32_t*)(g_Atl + base0 + col) = lo;
        pk2(O[nb][2] * i1, O[nb][3] * i1, hi, lo);
        *(uint32_t*)(g_Ath + base1 + col) = hi;
        *(uint32_t*)(g_Atl + base1 + col) = lo;
    }
}

// ---------------------------------------------------------------------------
extern "C" void kernel_launch(void* const* d_in, const int* in_sizes, int n_in,
                              void* d_out, int out_size)
{
    (void)in_sizes; (void)n_in; (void)out_size;
    const float* x  = (const float*)d_in[0];
    const float* Wq = (const float*)d_in[1];
    const float* Wk = (const float*)d_in[2];
    const float* Wv = (const float*)d_in[3];
    const float* Wo = (const float*)d_in[4];
    float* out = (float*)d_out;

    __nv_bfloat16 *xh, *xl, *wh, *wl, *woh, *wol, *ath, *atl;
    cudaGetSymbolAddress((void**)&xh, g_xh);   cudaGetSymbolAddress((void**)&xl, g_xl);
    cudaGetSymbolAddress((void**)&wh, g_Wh);   cudaGetSymbolAddress((void**)&wl, g_Wl);
    cudaGetSymbolAddress((void**)&woh, g_Woh); cudaGetSymbolAddress((void**)&wol, g_Wol);
    cudaGetSymbolAddress((void**)&ath, g_Ath); cudaGetSymbolAddress((void**)&atl, g_Atl);

    cudaFuncSetAttribute(gemm_bf16s<0>, cudaFuncAttributeMaxDynamicSharedMemorySize, GEMM_SMEM);
    cudaFuncSetAttribute(gemm_bf16s<1>, cudaFuncAttributeMaxDynamicSharedMemorySize, GEMM_SMEM);
    cudaFuncSetAttribute(attn_mma, cudaFuncAttributeMaxDynamicSharedMemorySize, ATT_SMEM);

    rope_table_k<<<(SS * 64 + 255) / 256, 256>>>();
    cvt_hl<<<(MR * HID / 4 + 255) / 256, 256>>>(x, xh, xl, MR * HID / 4);
    cvt_qkv<<<(GK * (NQKV / 4) + 255) / 256, 256>>>(Wq, Wk, Wv);
    cvt_hl<<<(HID * HID / 4 + 255) / 256, 256>>>(Wo, woh, wol, HID * HID / 4);

    // fused QKV projection + RoPE + split (one launch, 1536 CTAs)
    gemm_bf16s<1><<<dim3(NQKV / 128, MR / 128), 256, GEMM_SMEM>>>(
        xh, xl, wh, wl, nullptr, NQKV);

    attn_mma<<<dim3(SS / 128, NHQ, BB), 256, ATT_SMEM>>>();

    gemm_bf16s<0><<<dim3(HID / 128, MR / 128), 256, GEMM_SMEM>>>(
        ath, atl, woh, wol, out, HID);
}

// round 16
// speedup vs baseline: 1.0960x; 1.0676x over previous
#include <cuda_runtime.h>
#include <cuda_bf16.h>
#include <cuda_fp16.h>
#include <math.h>
#include <stdint.h>

#define BB 2
#define SS 2048
#define HID 4096
#define NHQ 32
#define NHKV 8
#define HD 128
#define MR (BB*SS)          // 4096 rows
#define KVD (NHKV*HD)       // 1024
#define GRP (NHQ/NHKV)      // 4
#define GK 4096             // all GEMMs have K=4096
#define NQKV (HID + 2*KVD)  // 6144 fused projection width

// ---------------- scratch (__device__ globals) ------------------------------
__device__ float g_cos[SS*(HD/2)];
__device__ float g_sin[SS*(HD/2)];
__device__ __half g_xh[MR*HID],  g_xl[MR*HID];          // x * 64, fp16 limbs
__device__ __half g_Wh[GK*NQKV], g_Wl[GK*NQKV];         // Wqkv * 64, fp16 limbs
__device__ __half g_Woh[HID*HID];                        // Wo * 64, fp16 hi only
__device__ __nv_bfloat16 g_Qh[MR*HID], g_Ql[MR*HID];    // attention inputs (bf16)
__device__ __nv_bfloat16 g_Kh[MR*KVD], g_Kl[MR*KVD];
__device__ __nv_bfloat16 g_Vh[MR*KVD], g_Vl[MR*KVD];
__device__ __half g_Ath[MR*HID], g_Atl[MR*HID];          // attn-out * 64, fp16 limbs

// ---------------- PTX helpers (portable sm_80-era ops) ----------------------
__device__ __forceinline__ uint32_t su32(const void* p) {
    uint32_t a;
    asm("{ .reg .u64 t; cvta.to.shared.u64 t, %1; cvt.u32.u64 %0, t; }"
        : "=r"(a) : "l"(p));
    return a;
}
__device__ __forceinline__ void cp16(uint32_t sa, const void* g) {
    asm volatile("cp.async.cg.shared.global [%0], [%1], 16;\n" :: "r"(sa), "l"(g));
}
#define CP_COMMIT() asm volatile("cp.async.commit_group;\n")
#define LDSM_X4(r, a) \
    asm volatile("ldmatrix.sync.aligned.m8n8.x4.shared.b16 {%0,%1,%2,%3}, [%4];" \
        : "=r"((r)[0]), "=r"((r)[1]), "=r"((r)[2]), "=r"((r)[3]) : "r"(a))
#define LDSM_X4T(r, a) \
    asm volatile("ldmatrix.sync.aligned.m8n8.x4.trans.shared.b16 {%0,%1,%2,%3}, [%4];" \
        : "=r"((r)[0]), "=r"((r)[1]), "=r"((r)[2]), "=r"((r)[3]) : "r"(a))
#define MMA4(d, a, b0, b1) \
    asm volatile("mma.sync.aligned.m16n8k16.row.col.f32.bf16.bf16.f32 " \
        "{%0,%1,%2,%3},{%4,%5,%6,%7},{%8,%9},{%0,%1,%2,%3};" \
        : "+f"((d)[0]), "+f"((d)[1]), "+f"((d)[2]), "+f"((d)[3]) \
        : "r"((a)[0]), "r"((a)[1]), "r"((a)[2]), "r"((a)[3]), "r"(b0), "r"(b1))
#define MMAH(d, a, b0, b1) \
    asm volatile("mma.sync.aligned.m16n8k16.row.col.f32.f16.f16.f32 " \
        "{%0,%1,%2,%3},{%4,%5,%6,%7},{%8,%9},{%0,%1,%2,%3};" \
        : "+f"((d)[0]), "+f"((d)[1]), "+f"((d)[2]), "+f"((d)[3]) \
        : "r"((a)[0]), "r"((a)[1]), "r"((a)[2]), "r"((a)[3]), "r"(b0), "r"(b1))

__device__ __forceinline__ uint32_t swz256(uint32_t o) {   // 256B rows
    return o ^ (((o >> 8) & 7u) << 4);
}
__device__ __forceinline__ uint32_t swz128(uint32_t o) {   // 128B rows
    return o ^ (((o >> 7) & 7u) << 4);
}
__device__ __forceinline__ void pk2(float x, float y, uint32_t& hi, uint32_t& lo) {
    __nv_bfloat16 hx = __float2bfloat16(x), hy = __float2bfloat16(y);
    hi = ((uint32_t)*(uint16_t*)&hy << 16) | *(uint16_t*)&hx;
    __nv_bfloat16 lx = __float2bfloat16(x - __bfloat162float(hx));
    __nv_bfloat16 ly = __float2bfloat16(y - __bfloat162float(hy));
    lo = ((uint32_t)*(uint16_t*)&ly << 16) | *(uint16_t*)&lx;
}
__device__ __forceinline__ void pk2h(float x, float y, uint32_t& hi, uint32_t& lo) {
    __half hx = __float2half_rn(x), hy = __float2half_rn(y);
    hi = ((uint32_t)*(uint16_t*)&hy << 16) | *(uint16_t*)&hx;
    __half lx = __float2half_rn(x - __half2float(hx));
    __half ly = __float2half_rn(y - __half2float(hy));
    lo = ((uint32_t)*(uint16_t*)&ly << 16) | *(uint16_t*)&lx;
}

// ---------------------------------------------------------------------------
// Split-fp16 tensor-core GEMM: C = A[M,4096] @ B[4096,N]  (A,B pre-scaled x64)
// MODE 1: fused QKV epilogue. Q,K cols 3-pass; V cols 2-pass (A-exact).
// MODE 0: Wo GEMM, 2-pass (Ah+Al)·Bh, B hi-only, fp32 out (descale 1/4096).
// CTA 128x128, BK=64, 3-stage, 256 threads, 8 warps of 64x32.
// ---------------------------------------------------------------------------
#define EPIT 130                 // epilogue smem pitch (floats)

template<int MODE>
__global__ void __launch_bounds__(256) gemm_f16(
    const __half* __restrict__ Ah, const __half* __restrict__ Al,
    const __half* __restrict__ Bh, const __half* __restrict__ Bl,
    float* __restrict__ Cf, int N)
{
    constexpr uint32_t BSTEP = (MODE == 1) ? 65536u : 49152u;
    extern __shared__ __align__(1024) char smg[];
    const uint32_t sb = su32(smg);
    const int tid = threadIdx.x, w = tid >> 5, l = tid & 31;
    const int n0 = blockIdx.x * 128, m0 = blockIdx.y * 128;
    const int wm = (w & 1) * 64, wn = (w >> 1) * 32;
    const bool threeP = (MODE == 1) && (n0 < HID + KVD);

    auto loadChunk = [&](int c, int stg) {
        const uint32_t st = sb + (uint32_t)stg * BSTEP;
        const int k0 = c * 64;
        #pragma unroll
        for (int t = 0; t < 4; t++) {                 // A: [128 m][64 k], 128B rows
            int j = tid + t * 256;
            int r = j >> 3, cc = j & 7;
            uint32_t o = swz128((uint32_t)(r * 128 + cc * 16));
            size_t g = (size_t)(m0 + r) * GK + k0 + cc * 8;
            cp16(st + o,         (const void*)(Ah + g));
            cp16(st + 16384 + o, (const void*)(Al + g));
        }
        #pragma unroll
        for (int t = 0; t < 4; t++) {                 // B: [64 k][128 n], 256B rows
            int j = tid + t * 256;
            int r = j >> 4, cc = j & 15;
            uint32_t o = swz256((uint32_t)(r * 256 + cc * 16));
            size_t g = (size_t)(k0 + r) * N + n0 + cc * 8;
            cp16(st + 32768 + o, (const void*)(Bh + g));
            if (threeP)
                cp16(st + 49152 + o, (const void*)(Bl + g));
        }
        CP_COMMIT();
    };

    float acc[4][4][4];
    #pragma unroll
    for (int mf = 0; mf < 4; mf++)
        #pragma unroll
        for (int nf = 0; nf < 4; nf++)
            { acc[mf][nf][0]=0.f; acc[mf][nf][1]=0.f; acc[mf][nf][2]=0.f; acc[mf][nf][3]=0.f; }

    loadChunk(0, 0);
    loadChunk(1, 1);

    const int NC = GK / 64;
    int stg = 0;
    for (int c = 0; c < NC; c++) {
        if (c + 1 < NC) {
            asm volatile("cp.async.wait_group 1;\n");
        } else {
            asm volatile("cp.async.wait_group 0;\n");
        }
        __syncthreads();
        int nstg = stg + 2; if (nstg >= 3) nstg -= 3;
        if (c + 2 < NC) loadChunk(c + 2, nstg);

        const uint32_t st = sb + (uint32_t)stg * BSTEP;
        #pragma unroll
        for (int ks = 0; ks < 4; ks++) {
            uint32_t ah[4][4], alr[4][4];
            #pragma unroll
            for (int mf = 0; mf < 4; mf++) {
                uint32_t adr = st + swz128((uint32_t)(
                    (wm + mf * 16 + (l & 15)) * 128 + ks * 32 + ((l & 16) ? 16 : 0)));
                LDSM_X4(ah[mf], adr);
                LDSM_X4(alr[mf], adr + 16384);
            }
            #pragma unroll
            for (int g = 0; g < 2; g++) {
                uint32_t br = (uint32_t)(ks * 16 + (l & 7) + ((l & 8) ? 8 : 0));
                uint32_t bc = (uint32_t)((wn + g * 16) * 2 + ((l & 16) ? 16 : 0));
                uint32_t badr = st + 32768 + swz256(br * 256 + bc);
                uint32_t bh[4];
                LDSM_X4T(bh, badr);
                #pragma unroll
                for (int mf = 0; mf < 4; mf++) {
                    MMAH(acc[mf][2*g],   ah[mf],  bh[0], bh[1]);
                    MMAH(acc[mf][2*g+1], ah[mf],  bh[2], bh[3]);
                    MMAH(acc[mf][2*g],   alr[mf], bh[0], bh[1]);
                    MMAH(acc[mf][2*g+1], alr[mf], bh[2], bh[3]);
                }
                if (threeP) {
                    uint32_t bl[4];
                    LDSM_X4T(bl, badr + 16384);
                    #pragma unroll
                    for (int mf = 0; mf < 4; mf++) {
                        MMAH(acc[mf][2*g],   ah[mf], bl[0], bl[1]);
                        MMAH(acc[mf][2*g+1], ah[mf], bl[2], bl[3]);
                    }
                }
            }
        }
        if (++stg >= 3) stg -= 3;
    }

    if (MODE == 0) {
        const float ds = 1.0f / 4096.0f;
        #pragma unroll
        for (int mf = 0; mf < 4; mf++) {
            int r0 = m0 + wm + mf * 16 + (l >> 2);
            #pragma unroll
            for (int nf = 0; nf < 4; nf++) {
                int cc = n0 + wn + nf * 8 + (l & 3) * 2;
                *(float2*)(Cf + (size_t)r0 * N + cc) =
                    make_float2(acc[mf][nf][0] * ds, acc[mf][nf][1] * ds);
                *(float2*)(Cf + (size_t)(r0 + 8) * N + cc) =
                    make_float2(acc[mf][nf][2] * ds, acc[mf][nf][3] * ds);
            }
        }
    } else {
        // fused RoPE + scale + split epilogue via smem exchange
        __syncthreads();
        float* sm = (float*)smg;
        #pragma unroll
        for (int mf = 0; mf < 4; mf++) {
            int r0 = wm + mf * 16 + (l >> 2);
            #pragma unroll
            for (int nf = 0; nf < 4; nf++) {
                int cc = wn + nf * 8 + (l & 3) * 2;
                *(float2*)(sm + r0 * EPIT + cc) =
                    make_float2(acc[mf][nf][0], acc[mf][nf][1]);
                *(float2*)(sm + (r0 + 8) * EPIT + cc) =
                    make_float2(acc[mf][nf][2], acc[mf][nf][3]);
            }
        }
        __syncthreads();

        __nv_bfloat16 *H, *L;
        int stride, colb;
        bool rope;
        float scale;
        if (n0 < HID)            { H = g_Qh; L = g_Ql; stride = HID; colb = n0;
                                   rope = true;  scale = 0.08838834764831845f / 4096.0f; }
        else if (n0 < HID + KVD) { H = g_Kh; L = g_Kl; stride = KVD; colb = n0 - HID;
                                   rope = true;  scale = 1.0f / 4096.0f; }
        else                     { H = g_Vh; L = g_Vl; stride = KVD; colb = n0 - HID - KVD;
                                   rope = false; scale = 1.0f / 4096.0f; }

        #pragma unroll 4
        for (int i = 0; i < 32; i++) {
            int idx = tid + i * 256;           // 128 rows x 64 halves
            int r = idx >> 6, half = idx & 63;
            float x1 = sm[r * EPIT + half];
            float x2 = sm[r * EPIT + half + 64];
            float cth = 1.f, sth = 0.f;
            int grow = m0 + r;
            if (rope) {
                int s = grow & (SS - 1);
                cth = g_cos[s * 64 + half];
                sth = g_sin[s * 64 + half];
            }
            float y1 = (x1 * cth - x2 * sth) * scale;
            float y2 = (x2 * cth + x1 * sth) * scale;
            __nv_bfloat16 h1 = __float2bfloat16(y1);
            __nv_bfloat16 h2 = __float2bfloat16(y2);
            size_t o = (size_t)grow * stride + colb + half;
            H[o]      = h1;
            H[o + 64] = h2;
            L[o]      = __float2bfloat16(y1 - __bfloat162float(h1));
            L[o + 64] = __float2bfloat16(y2 - __bfloat162float(h2));
        }
    }
}

// ---------------------------------------------------------------------------
// conversions & RoPE table
// ---------------------------------------------------------------------------
__global__ void cvt_xh(const float* __restrict__ X,
                       __half* __restrict__ H, __half* __restrict__ L, int n4)
{
    int i = blockIdx.x * 256 + threadIdx.x;
    if (i >= n4) return;
    float4 v = *(const float4*)(X + (size_t)i * 4);
    uint32_t h01, l01, h23, l23;
    pk2h(v.x * 64.f, v.y * 64.f, h01, l01);
    pk2h(v.z * 64.f, v.w * 64.f, h23, l23);
    *(uint2*)(H + (size_t)i * 4) = make_uint2(h01, h23);
    *(uint2*)(L + (size_t)i * 4) = make_uint2(l01, l23);
}

// concat Wq|Wk|Wv (all [K, n]) into [K, 6144] fp16 limbs, scaled x64
__global__ void cvt_qkv(const float* __restrict__ Wq, const float* __restrict__ Wk,
                        const float* __restrict__ Wv)
{
    int i = blockIdx.x * 256 + threadIdx.x;
    if (i >= GK * (NQKV / 4)) return;
    int k = i / (NQKV / 4);
    int n = (i - k * (NQKV / 4)) * 4;
    const float* src;
    if (n < HID)            src = Wq + (size_t)k * HID + n;
    else if (n < HID + KVD) src = Wk + (size_t)k * KVD + (n - HID);
    else                    src = Wv + (size_t)k * KVD + (n - HID - KVD);
    float4 v = *(const float4*)src;
    uint32_t h01, l01, h23, l23;
    pk2h(v.x * 64.f, v.y * 64.f, h01, l01);
    pk2h(v.z * 64.f, v.w * 64.f, h23, l23);
    size_t o = (size_t)k * NQKV + n;
    *(uint2*)(g_Wh + o) = make_uint2(h01, h23);
    *(uint2*)(g_Wl + o) = make_uint2(l01, l23);
}

// Wo -> fp16 hi only, scaled x64
__global__ void cvt_woh(const float* __restrict__ W, __half* __restrict__ H, int n4)
{
    int i = blockIdx.x * 256 + threadIdx.x;
    if (i >= n4) return;
    float4 v = *(const float4*)(W + (size_t)i * 4);
    __half h0 = __float2half_rn(v.x * 64.f), h1 = __float2half_rn(v.y * 64.f);
    __half h2 = __float2half_rn(v.z * 64.f), h3 = __float2half_rn(v.w * 64.f);
    uint32_t a = ((uint32_t)*(uint16_t*)&h1 << 16) | *(uint16_t*)&h0;
    uint32_t b = ((uint32_t)*(uint16_t*)&h3 << 16) | *(uint16_t*)&h2;
    *(uint2*)(H + (size_t)i * 4) = make_uint2(a, b);
}

__global__ void rope_table_k()
{
    int idx = blockIdx.x * blockDim.x + threadIdx.x;
    if (idx >= SS * 64) return;
    int pos = idx >> 6;
    int i   = idx & 63;
    float invf = (float)pow(10000.0, -((double)i) / 64.0);
    float angf = (float)pos * invf;
    double ang = (double)angf;
    g_cos[idx] = (float)cos(ang);
    g_sin[idx] = (float)sin(ang);
}

// ---------------------------------------------------------------------------
// FlashAttention-2 mma.sync bf16 split (proven kernel; epilogue now emits
// fp16 limbs scaled x64 for the Wo GEMM).
// ---------------------------------------------------------------------------
#define ATT_SMEM 196608

__global__ void __launch_bounds__(256) attn_mma()
{
    extern __shared__ __align__(1024) char smdyn[];
    const int qb = (int)gridDim.x - 1 - (int)blockIdx.x;   // largest first
    const int h = blockIdx.y, b = blockIdx.z;
    const int kvh = h / GRP;
    const int tid = threadIdx.x, w = tid >> 5, l = tid & 31;
    const uint32_t sb = su32(smdyn);
    const uint32_t Qh_s = sb;
    const uint32_t KV0  = sb + 65536;

    {
        const __nv_bfloat16* qh = g_Qh + (size_t)(b * SS + qb * 128) * HID + h * HD;
        const __nv_bfloat16* ql = g_Ql + (size_t)(b * SS + qb * 128) * HID + h * HD;
        #pragma unroll
        for (int t = 0; t < 8; t++) {
            int j = tid + t * 256;
            int r = j >> 4, c = j & 15;
            uint32_t o = swz256((uint32_t)(r * 256 + c * 16));
            cp16(Qh_s + o,         (const void*)(qh + (size_t)r * HID + c * 8));
            cp16(Qh_s + 32768 + o, (const void*)(ql + (size_t)r * HID + c * 8));
        }
        CP_COMMIT();
    }

    const int NT = 2 * qb + 2;
    auto loadKV = [&](int kt) {
        const uint32_t st = KV0 + (uint32_t)(kt & 1) * 65536;
        const size_t rb = (size_t)(b * SS + kt * 64) * KVD + kvh * HD;
        #pragma unroll
        for (int t = 0; t < 4; t++) {
            int j = tid + t * 256;
            int r = j >> 4, c = j & 15;
            uint32_t o = swz256((uint32_t)(r * 256 + c * 16));
            size_t g = rb + (size_t)r * KVD + c * 8;
            cp16(st +         o, (const void*)(g_Kh + g));
            cp16(st + 16384 + o, (const void*)(g_Kl + g));
            cp16(st + 32768 + o, (const void*)(g_Vh + g));
            cp16(st + 49152 + o, (const void*)(g_Vl + g));
        }
        CP_COMMIT();
    };
    loadKV(0);

    const int m0 = w * 16;
    const int qg0 = qb * 128 + m0 + (l >> 2);
    float O[16][4];
    #pragma unroll
    for (int f = 0; f < 16; f++)
        { O[f][0] = 0.f; O[f][1] = 0.f; O[f][2] = 0.f; O[f][3] = 0.f; }
    float mr0 = -1e30f, mr1 = -1e30f, sl0 = 0.f, sl1 = 0.f;

    for (int kt = 0; kt < NT; kt++) {
        if (kt + 1 < NT) {
            loadKV(kt + 1);
            asm volatile("cp.async.wait_group 1;\n");
        } else {
            asm volatile("cp.async.wait_group 0;\n");
        }
        __syncthreads();

        const uint32_t st = KV0 + (uint32_t)(kt & 1) * 65536;

        float s[8][4];
        #pragma unroll
        for (int nb = 0; nb < 8; nb++)
            { s[nb][0] = 0.f; s[nb][1] = 0.f; s[nb][2] = 0.f; s[nb][3] = 0.f; }

        #pragma unroll
        for (int ks = 0; ks < 8; ks++) {
            uint32_t aQh[4], aQl[4];
            uint32_t aaddr = Qh_s + swz256(
                (uint32_t)((m0 + (l & 15)) * 256 + ks * 32 + ((l & 16) ? 16 : 0)));
            LDSM_X4(aQh, aaddr);
            LDSM_X4(aQl, aaddr + 32768);
            #pragma unroll
            for (int nb2 = 0; nb2 < 4; nb2++) {
                uint32_t brow = (uint32_t)(nb2 * 16 + (l & 7) + ((l & 16) ? 8 : 0));
                uint32_t baddr = st + swz256(brow * 256 + ks * 32 + ((l & 8) ? 16 : 0));
                uint32_t bh[4], bl[4];
                LDSM_X4(bh, baddr);
                LDSM_X4(bl, baddr + 16384);
                MMA4(s[2*nb2],   aQh, bh[0], bh[1]);
                MMA4(s[2*nb2+1], aQh, bh[2], bh[3]);
                MMA4(s[2*nb2],   aQh, bl[0], bl[1]);
                MMA4(s[2*nb2+1], aQh, bl[2], bl[3]);
                MMA4(s[2*nb2],   aQl, bh[0], bh[1]);
                MMA4(s[2*nb2+1], aQl, bh[2], bh[3]);
            }
        }

        const int kgb = kt * 64 + (l & 3) * 2;
        float mx0 = -1e30f, mx1 = -1e30f;
        #pragma unroll
        for (int nb = 0; nb < 8; nb++) {
            int kg = kgb + nb * 8;
            if (kg     > qg0)     s[nb][0] = -1e30f;
            if (kg + 1 > qg0)     s[nb][1] = -1e30f;
            if (kg     > qg0 + 8) s[nb][2] = -1e30f;
            if (kg + 1 > qg0 + 8) s[nb][3] = -1e30f;
            mx0 = fmaxf(mx0, fmaxf(s[nb][0], s[nb][1]));
            mx1 = fmaxf(mx1, fmaxf(s[nb][2], s[nb][3]));
        }
        mx0 = fmaxf(mx0, __shfl_xor_sync(0xffffffffu, mx0, 1));
        mx0 = fmaxf(mx0, __shfl_xor_sync(0xffffffffu, mx0, 2));
        mx1 = fmaxf(mx1, __shfl_xor_sync(0xffffffffu, mx1, 1));
        mx1 = fmaxf(mx1, __shfl_xor_sync(0xffffffffu, mx1, 2));

        float mn0 = fmaxf(mr0, mx0), mn1 = fmaxf(mr1, mx1);
        float al0 = __expf(mr0 - mn0), al1 = __expf(mr1 - mn1);
        mr0 = mn0; mr1 = mn1;
        float sum0 = 0.f, sum1 = 0.f;
        #pragma unroll
        for (int nb = 0; nb < 8; nb++) {
            s[nb][0] = __expf(s[nb][0] - mn0);
            s[nb][1] = __expf(s[nb][1] - mn0);
            s[nb][2] = __expf(s[nb][2] - mn1);
            s[nb][3] = __expf(s[nb][3] - mn1);
            sum0 += s[nb][0] + s[nb][1];
            sum1 += s[nb][2] + s[nb][3];
        }
        sum0 += __shfl_xor_sync(0xffffffffu, sum0, 1);
        sum0 += __shfl_xor_sync(0xffffffffu, sum0, 2);
        sum1 += __shfl_xor_sync(0xffffffffu, sum1, 1);
        sum1 += __shfl_xor_sync(0xffffffffu, sum1, 2);
        sl0 = sl0 * al0 + sum0;
        sl1 = sl1 * al1 + sum1;
        #pragma unroll
        for (int f = 0; f < 16; f++) {
            O[f][0] *= al0; O[f][1] *= al0; O[f][2] *= al1; O[f][3] *= al1;
        }

        #pragma unroll
        for (int j = 0; j < 4; j++) {
            uint32_t ph[4], pl[4];
            pk2(s[2*j][0],   s[2*j][1],   ph[0], pl[0]);
            pk2(s[2*j][2],   s[2*j][3],   ph[1], pl[1]);
            pk2(s[2*j+1][0], s[2*j+1][1], ph[2], pl[2]);
            pk2(s[2*j+1][2], s[2*j+1][3], ph[3], pl[3]);
            uint32_t vrow = (uint32_t)(j * 16 + (l & 7) + ((l & 8) ? 8 : 0));
            #pragma unroll
            for (int nb2 = 0; nb2 < 8; nb2++) {
                uint32_t vaddr = st + 32768 +
                    swz256(vrow * 256 + nb2 * 32 + ((l & 16) ? 16 : 0));
                uint32_t vh[4], vl[4];
                LDSM_X4T(vh, vaddr);
                LDSM_X4T(vl, vaddr + 16384);
                MMA4(O[2*nb2],   ph, vh[0], vh[1]);
                MMA4(O[2*nb2+1], ph, vh[2], vh[3]);
                MMA4(O[2*nb2],   ph, vl[0], vl[1]);
                MMA4(O[2*nb2+1], ph, vl[2], vl[3]);
                MMA4(O[2*nb2],   pl, vh[0], vh[1]);
                MMA4(O[2*nb2+1], pl, vh[2], vh[3]);
            }
        }
        __syncthreads();
    }

    // epilogue: normalize, scale x64, split to fp16 limbs for Wo GEMM
    const float i0 = 64.0f / sl0, i1 = 64.0f / sl1;
    size_t base0 = (size_t)(b * SS + qg0) * HID + (size_t)h * HD;
    size_t base1 = base0 + (size_t)8 * HID;
    #pragma unroll
    for (int nb = 0; nb < 16; nb++) {
        int col = nb * 8 + (l & 3) * 2;
        uint32_t hi, lo;
        pk2h(O[nb][0] * i0, O[nb][1] * i0, hi, lo);
        *(uint32_t*)(g_Ath + base0 + col) = hi;
        *(uint32_t*)(g_Atl + base0 + col) = lo;
        pk2h(O[nb][2] * i1, O[nb][3] * i1, hi, lo);
        *(uint32_t*)(g_Ath + base1 + col) = hi;
        *(uint32_t*)(g_Atl + base1 + col) = lo;
    }
}

// ---------------------------------------------------------------------------
extern "C" void kernel_launch(void* const* d_in, const int* in_sizes, int n_in,
                              void* d_out, int out_size)
{
    (void)in_sizes; (void)n_in; (void)out_size;
    const float* x  = (const float*)d_in[0];
    const float* Wq = (const float*)d_in[1];
    const float* Wk = (const float*)d_in[2];
    const float* Wv = (const float*)d_in[3];
    const float* Wo = (const float*)d_in[4];
    float* out = (float*)d_out;

    __half *xh, *xl, *wh, *wl, *woh, *ath, *atl;
    cudaGetSymbolAddress((void**)&xh, g_xh);   cudaGetSymbolAddress((void**)&xl, g_xl);
    cudaGetSymbolAddress((void**)&wh, g_Wh);   cudaGetSymbolAddress((void**)&wl, g_Wl);
    cudaGetSymbolAddress((void**)&woh, g_Woh);
    cudaGetSymbolAddress((void**)&ath, g_Ath); cudaGetSymbolAddress((void**)&atl, g_Atl);

    cudaFuncSetAttribute(gemm_f16<1>, cudaFuncAttributeMaxDynamicSharedMemorySize, 196608);
    cudaFuncSetAttribute(gemm_f16<0>, cudaFuncAttributeMaxDynamicSharedMemorySize, 147456);
    cudaFuncSetAttribute(attn_mma, cudaFuncAttributeMaxDynamicSharedMemorySize, ATT_SMEM);

    rope_table_k<<<(SS * 64 + 255) / 256, 256>>>();
    cvt_xh<<<(MR * HID / 4 + 255) / 256, 256>>>(x, xh, xl, MR * HID / 4);
    cvt_qkv<<<(GK * (NQKV / 4) + 255) / 256, 256>>>(Wq, Wk, Wv);
    cvt_woh<<<(HID * HID / 4 + 255) / 256, 256>>>(Wo, woh, HID * HID / 4);

    // fused QKV projection + RoPE + split (Q,K 3-pass; V 2-pass)
    gemm_f16<1><<<dim3(NQKV / 128, MR / 128), 256, 196608>>>(
        xh, xl, wh, wl, nullptr, NQKV);

    attn_mma<<<dim3(SS / 128, NHQ, BB), 256, ATT_SMEM>>>();

    // output projection (2-pass, B hi-only)
    gemm_f16<0><<<dim3(HID / 128, MR / 128), 256, 147456>>>(
        ath, atl, woh, nullptr, out, HID);
}

// round 17
// speedup vs baseline: 1.3164x; 1.2011x over previous
#include <cuda_runtime.h>
#include <cuda_bf16.h>
#include <cuda_fp16.h>
#include <math.h>
#include <stdint.h>

#define BB 2
#define SS 2048
#define HID 4096
#define NHQ 32
#define NHKV 8
#define HD 128
#define MR (BB*SS)          // 4096 rows
#define KVD (NHKV*HD)       // 1024
#define GRP (NHQ/NHKV)      // 4
#define GK 4096             // all GEMMs have K=4096
#define NQKV (HID + 2*KVD)  // 6144 fused projection width

// ---------------- scratch (__device__ globals) ------------------------------
__device__ float g_cos[SS*(HD/2)];
__device__ float g_sin[SS*(HD/2)];
__device__ __half g_xh[MR*HID],  g_xl[MR*HID];          // x * 64, fp16 limbs
__device__ __half g_Wh[GK*NQKV], g_Wl[GK*NQKV];         // Wqkv * 64, fp16 limbs
__device__ __half g_Woh[HID*HID];                        // Wo * 64, fp16 hi only
__device__ __nv_bfloat16 g_Qh[MR*HID], g_Ql[MR*HID];    // attention Q (bf16 limbs)
__device__ __nv_bfloat16 g_Kh[MR*KVD], g_Kl[MR*KVD];    // attention K (bf16 limbs)
__device__ __half g_V[MR*KVD];                           // attention V (fp16 single)
__device__ __half g_At[MR*HID];                          // attn-out * 64, fp16 single

// ---------------- PTX helpers (portable sm_80-era ops) ----------------------
__device__ __forceinline__ uint32_t su32(const void* p) {
    uint32_t a;
    asm("{ .reg .u64 t; cvta.to.shared.u64 t, %1; cvt.u32.u64 %0, t; }"
        : "=r"(a) : "l"(p));
    return a;
}
__device__ __forceinline__ void cp16(uint32_t sa, const void* g) {
    asm volatile("cp.async.cg.shared.global [%0], [%1], 16;\n" :: "r"(sa), "l"(g));
}
#define CP_COMMIT() asm volatile("cp.async.commit_group;\n")
#define LDSM_X4(r, a) \
    asm volatile("ldmatrix.sync.aligned.m8n8.x4.shared.b16 {%0,%1,%2,%3}, [%4];" \
        : "=r"((r)[0]), "=r"((r)[1]), "=r"((r)[2]), "=r"((r)[3]) : "r"(a))
#define LDSM_X4T(r, a) \
    asm volatile("ldmatrix.sync.aligned.m8n8.x4.trans.shared.b16 {%0,%1,%2,%3}, [%4];" \
        : "=r"((r)[0]), "=r"((r)[1]), "=r"((r)[2]), "=r"((r)[3]) : "r"(a))
#define MMA4(d, a, b0, b1) \
    asm volatile("mma.sync.aligned.m16n8k16.row.col.f32.bf16.bf16.f32 " \
        "{%0,%1,%2,%3},{%4,%5,%6,%7},{%8,%9},{%0,%1,%2,%3};" \
        : "+f"((d)[0]), "+f"((d)[1]), "+f"((d)[2]), "+f"((d)[3]) \
        : "r"((a)[0]), "r"((a)[1]), "r"((a)[2]), "r"((a)[3]), "r"(b0), "r"(b1))
#define MMAH(d, a, b0, b1) \
    asm volatile("mma.sync.aligned.m16n8k16.row.col.f32.f16.f16.f32 " \
        "{%0,%1,%2,%3},{%4,%5,%6,%7},{%8,%9},{%0,%1,%2,%3};" \
        : "+f"((d)[0]), "+f"((d)[1]), "+f"((d)[2]), "+f"((d)[3]) \
        : "r"((a)[0]), "r"((a)[1]), "r"((a)[2]), "r"((a)[3]), "r"(b0), "r"(b1))

__device__ __forceinline__ uint32_t swz256(uint32_t o) {   // 256B rows
    return o ^ (((o >> 8) & 7u) << 4);
}
__device__ __forceinline__ uint32_t swz128(uint32_t o) {   // 128B rows
    return o ^ (((o >> 7) & 7u) << 4);
}
__device__ __forceinline__ void pk2(float x, float y, uint32_t& hi, uint32_t& lo) {
    __nv_bfloat16 hx = __float2bfloat16(x), hy = __float2bfloat16(y);
    hi = ((uint32_t)*(uint16_t*)&hy << 16) | *(uint16_t*)&hx;
    __nv_bfloat16 lx = __float2bfloat16(x - __bfloat162float(hx));
    __nv_bfloat16 ly = __float2bfloat16(y - __bfloat162float(hy));
    lo = ((uint32_t)*(uint16_t*)&ly << 16) | *(uint16_t*)&lx;
}
__device__ __forceinline__ void pk2h(float x, float y, uint32_t& hi, uint32_t& lo) {
    __half hx = __float2half_rn(x), hy = __float2half_rn(y);
    hi = ((uint32_t)*(uint16_t*)&hy << 16) | *(uint16_t*)&hx;
    __half lx = __float2half_rn(x - __half2float(hx));
    __half ly = __float2half_rn(y - __half2float(hy));
    lo = ((uint32_t)*(uint16_t*)&ly << 16) | *(uint16_t*)&lx;
}
__device__ __forceinline__ uint32_t pkh(float x, float y) {
    __half2 h = __floats2half2_rn(x, y);
    return *(uint32_t*)&h;
}

// ---------------------------------------------------------------------------
// Split-fp16 tensor-core GEMM: C = A[M,4096] @ B[4096,N]  (A,B pre-scaled x64)
// MODE 1: fused QKV. Q,K cols 3-pass; V cols 2-pass; epilogue RoPE+split.
// MODE 0: Wo GEMM, 1-pass Ah·Bh, fp32 out (descale 1/4096). 96KB smem.
// CTA 128x128, BK=64, 3-stage, 256 threads, 8 warps of 64x32.
// ---------------------------------------------------------------------------
#define EPIT 130                 // epilogue smem pitch (floats)

template<int MODE>
__global__ void __launch_bounds__(256) gemm_f16(
    const __half* __restrict__ Ah, const __half* __restrict__ Al,
    const __half* __restrict__ Bh, const __half* __restrict__ Bl,
    float* __restrict__ Cf, int N)
{
    constexpr uint32_t BSTEP = (MODE == 1) ? 65536u : 32768u;
    constexpr uint32_t BOFF  = (MODE == 1) ? 32768u : 16384u;
    extern __shared__ __align__(1024) char smg[];
    const uint32_t sb = su32(smg);
    const int tid = threadIdx.x, w = tid >> 5, l = tid & 31;
    const int n0 = blockIdx.x * 128, m0 = blockIdx.y * 128;
    const int wm = (w & 1) * 64, wn = (w >> 1) * 32;
    const bool threeP = (MODE == 1) && (n0 < HID + KVD);

    auto loadChunk = [&](int c, int stg) {
        const uint32_t st = sb + (uint32_t)stg * BSTEP;
        const int k0 = c * 64;
        #pragma unroll
        for (int t = 0; t < 4; t++) {                 // A: [128 m][64 k], 128B rows
            int j = tid + t * 256;
            int r = j >> 3, cc = j & 7;
            uint32_t o = swz128((uint32_t)(r * 128 + cc * 16));
            size_t g = (size_t)(m0 + r) * GK + k0 + cc * 8;
            cp16(st + o, (const void*)(Ah + g));
            if (MODE == 1)
                cp16(st + 16384 + o, (const void*)(Al + g));
        }
        #pragma unroll
        for (int t = 0; t < 4; t++) {                 // B: [64 k][128 n], 256B rows
            int j = tid + t * 256;
            int r = j >> 4, cc = j & 15;
            uint32_t o = swz256((uint32_t)(r * 256 + cc * 16));
            size_t g = (size_t)(k0 + r) * N + n0 + cc * 8;
            cp16(st + BOFF + o, (const void*)(Bh + g));
            if (threeP)
                cp16(st + BOFF + 16384 + o, (const void*)(Bl + g));
        }
        CP_COMMIT();
    };

    float acc[4][4][4];
    #pragma unroll
    for (int mf = 0; mf < 4; mf++)
        #pragma unroll
        for (int nf = 0; nf < 4; nf++)
            { acc[mf][nf][0]=0.f; acc[mf][nf][1]=0.f; acc[mf][nf][2]=0.f; acc[mf][nf][3]=0.f; }

    loadChunk(0, 0);
    loadChunk(1, 1);

    const int NC = GK / 64;
    int stg = 0;
    for (int c = 0; c < NC; c++) {
        if (c + 1 < NC) {
            asm volatile("cp.async.wait_group 1;\n");
        } else {
            asm volatile("cp.async.wait_group 0;\n");
        }
        __syncthreads();
        int nstg = stg + 2; if (nstg >= 3) nstg -= 3;
        if (c + 2 < NC) loadChunk(c + 2, nstg);

        const uint32_t st = sb + (uint32_t)stg * BSTEP;
        #pragma unroll
        for (int ks = 0; ks < 4; ks++) {
            uint32_t ah[4][4], alr[4][4];
            #pragma unroll
            for (int mf = 0; mf < 4; mf++) {
                uint32_t adr = st + swz128((uint32_t)(
                    (wm + mf * 16 + (l & 15)) * 128 + ks * 32 + ((l & 16) ? 16 : 0)));
                LDSM_X4(ah[mf], adr);
                if (MODE == 1)
                    LDSM_X4(alr[mf], adr + 16384);
            }
            #pragma unroll
            for (int g = 0; g < 2; g++) {
                uint32_t br = (uint32_t)(ks * 16 + (l & 7) + ((l & 8) ? 8 : 0));
                uint32_t bc = (uint32_t)((wn + g * 16) * 2 + ((l & 16) ? 16 : 0));
                uint32_t badr = st + BOFF + swz256(br * 256 + bc);
                uint32_t bh[4];
                LDSM_X4T(bh, badr);
                #pragma unroll
                for (int mf = 0; mf < 4; mf++) {
                    MMAH(acc[mf][2*g],   ah[mf], bh[0], bh[1]);
                    MMAH(acc[mf][2*g+1], ah[mf], bh[2], bh[3]);
                    if (MODE == 1) {
                        MMAH(acc[mf][2*g],   alr[mf], bh[0], bh[1]);
                        MMAH(acc[mf][2*g+1], alr[mf], bh[2], bh[3]);
                    }
                }
                if (threeP) {
                    uint32_t bl[4];
                    LDSM_X4T(bl, badr + 16384);
                    #pragma unroll
                    for (int mf = 0; mf < 4; mf++) {
                        MMAH(acc[mf][2*g],   ah[mf], bl[0], bl[1]);
                        MMAH(acc[mf][2*g+1], ah[mf], bl[2], bl[3]);
                    }
                }
            }
        }
        if (++stg >= 3) stg -= 3;
    }

    if (MODE == 0) {
        const float ds = 1.0f / 4096.0f;
        #pragma unroll
        for (int mf = 0; mf < 4; mf++) {
            int r0 = m0 + wm + mf * 16 + (l >> 2);
            #pragma unroll
            for (int nf = 0; nf < 4; nf++) {
                int cc = n0 + wn + nf * 8 + (l & 3) * 2;
                *(float2*)(Cf + (size_t)r0 * N + cc) =
                    make_float2(acc[mf][nf][0] * ds, acc[mf][nf][1] * ds);
                *(float2*)(Cf + (size_t)(r0 + 8) * N + cc) =
                    make_float2(acc[mf][nf][2] * ds, acc[mf][nf][3] * ds);
            }
        }
    } else {
        // fused RoPE + scale + split epilogue via smem exchange
        __syncthreads();
        float* sm = (float*)smg;
        #pragma unroll
        for (int mf = 0; mf < 4; mf++) {
            int r0 = wm + mf * 16 + (l >> 2);
            #pragma unroll
            for (int nf = 0; nf < 4; nf++) {
                int cc = wn + nf * 8 + (l & 3) * 2;
                *(float2*)(sm + r0 * EPIT + cc) =
                    make_float2(acc[mf][nf][0], acc[mf][nf][1]);
                *(float2*)(sm + (r0 + 8) * EPIT + cc) =
                    make_float2(acc[mf][nf][2], acc[mf][nf][3]);
            }
        }
        __syncthreads();

        const float ds = 1.0f / 4096.0f;
        if (n0 < HID + KVD) {
            // Q or K: RoPE + split bf16 hi/lo
            __nv_bfloat16 *H, *L;
            int stride, colb;
            float scale;
            if (n0 < HID) { H = g_Qh; L = g_Ql; stride = HID; colb = n0;
                            scale = 0.08838834764831845f * ds; }
            else          { H = g_Kh; L = g_Kl; stride = KVD; colb = n0 - HID;
                            scale = ds; }
            #pragma unroll 4
            for (int i = 0; i < 32; i++) {
                int idx = tid + i * 256;           // 128 rows x 64 halves
                int r = idx >> 6, half = idx & 63;
                float x1 = sm[r * EPIT + half];
                float x2 = sm[r * EPIT + half + 64];
                int grow = m0 + r;
                int s = grow & (SS - 1);
                float cth = g_cos[s * 64 + half];
                float sth = g_sin[s * 64 + half];
                float y1 = (x1 * cth - x2 * sth) * scale;
                float y2 = (x2 * cth + x1 * sth) * scale;
                __nv_bfloat16 h1 = __float2bfloat16(y1);
                __nv_bfloat16 h2 = __float2bfloat16(y2);
                size_t o = (size_t)grow * stride + colb + half;
                H[o]      = h1;
                H[o + 64] = h2;
                L[o]      = __float2bfloat16(y1 - __bfloat162float(h1));
                L[o + 64] = __float2bfloat16(y2 - __bfloat162float(h2));
            }
        } else {
            // V: single fp16 store
            int colb = n0 - HID - KVD;
            #pragma unroll 4
            for (int i = 0; i < 64; i++) {
                int idx = tid + i * 256;           // 128 rows x 128 cols
                int r = idx >> 7, cc = idx & 127;
                float y = sm[r * EPIT + cc] * ds;
                g_V[(size_t)(m0 + r) * KVD + colb + cc] = __float2half_rn(y);
            }
        }
    }
}

// ---------------------------------------------------------------------------
// conversions & RoPE table
// ---------------------------------------------------------------------------
__global__ void cvt_xh(const float* __restrict__ X,
                       __half* __restrict__ H, __half* __restrict__ L, int n4)
{
    int i = blockIdx.x * 256 + threadIdx.x;
    if (i >= n4) return;
    float4 v = *(const float4*)(X + (size_t)i * 4);
    uint32_t h01, l01, h23, l23;
    pk2h(v.x * 64.f, v.y * 64.f, h01, l01);
    pk2h(v.z * 64.f, v.w * 64.f, h23, l23);
    *(uint2*)(H + (size_t)i * 4) = make_uint2(h01, h23);
    *(uint2*)(L + (size_t)i * 4) = make_uint2(l01, l23);
}

// concat Wq|Wk|Wv (all [K, n]) into [K, 6144] fp16 limbs, scaled x64
__global__ void cvt_qkv(const float* __restrict__ Wq, const float* __restrict__ Wk,
                        const float* __restrict__ Wv)
{
    int i = blockIdx.x * 256 + threadIdx.x;
    if (i >= GK * (NQKV / 4)) return;
    int k = i / (NQKV / 4);
    int n = (i - k * (NQKV / 4)) * 4;
    const float* src;
    if (n < HID)            src = Wq + (size_t)k * HID + n;
    else if (n < HID + KVD) src = Wk + (size_t)k * KVD + (n - HID);
    else                    src = Wv + (size_t)k * KVD + (n - HID - KVD);
    float4 v = *(const float4*)src;
    uint32_t h01, l01, h23, l23;
    pk2h(v.x * 64.f, v.y * 64.f, h01, l01);
    pk2h(v.z * 64.f, v.w * 64.f, h23, l23);
    size_t o = (size_t)k * NQKV + n;
    *(uint2*)(g_Wh + o) = make_uint2(h01, h23);
    *(uint2*)(g_Wl + o) = make_uint2(l01, l23);
}

// Wo -> fp16 hi only, scaled x64
__global__ void cvt_woh(const float* __restrict__ W, __half* __restrict__ H, int n4)
{
    int i = blockIdx.x * 256 + threadIdx.x;
    if (i >= n4) return;
    float4 v = *(const float4*)(W + (size_t)i * 4);
    uint32_t a = pkh(v.x * 64.f, v.y * 64.f);
    uint32_t b = pkh(v.z * 64.f, v.w * 64.f);
    *(uint2*)(H + (size_t)i * 4) = make_uint2(a, b);
}

__global__ void rope_table_k()
{
    int idx = blockIdx.x * blockDim.x + threadIdx.x;
    if (idx >= SS * 64) return;
    int pos = idx >> 6;
    int i   = idx & 63;
    float invf = (float)pow(10000.0, -((double)i) / 64.0);
    float angf = (float)pos * invf;
    double ang = (double)angf;
    g_cos[idx] = (float)cos(ang);
    g_sin[idx] = (float)sin(ang);
}

// ---------------------------------------------------------------------------
// FlashAttention-2: S = bf16 3-pass (unchanged), PV = fp16 single P x single V
// (2 MMAs per fragment pair). KV stage: Kh 16KB | Kl 16KB | V 16KB = 48KB.
// ---------------------------------------------------------------------------
#define ATT_SMEM (65536 + 2*49152)

__global__ void __launch_bounds__(256) attn_mma()
{
    extern __shared__ __align__(1024) char smdyn[];
    const int qb = (int)gridDim.x - 1 - (int)blockIdx.x;   // largest first
    const int h = blockIdx.y, b = blockIdx.z;
    const int kvh = h / GRP;
    const int tid = threadIdx.x, w = tid >> 5, l = tid & 31;
    const uint32_t sb = su32(smdyn);
    const uint32_t Qh_s = sb;
    const uint32_t KV0  = sb + 65536;

    {
        const __nv_bfloat16* qh = g_Qh + (size_t)(b * SS + qb * 128) * HID + h * HD;
        const __nv_bfloat16* ql = g_Ql + (size_t)(b * SS + qb * 128) * HID + h * HD;
        #pragma unroll
        for (int t = 0; t < 8; t++) {
            int j = tid + t * 256;
            int r = j >> 4, c = j & 15;
            uint32_t o = swz256((uint32_t)(r * 256 + c * 16));
            cp16(Qh_s + o,         (const void*)(qh + (size_t)r * HID + c * 8));
            cp16(Qh_s + 32768 + o, (const void*)(ql + (size_t)r * HID + c * 8));
        }
        CP_COMMIT();
    }

    const int NT = 2 * qb + 2;
    auto loadKV = [&](int kt) {
        const uint32_t st = KV0 + (uint32_t)(kt & 1) * 49152;
        const size_t rb = (size_t)(b * SS + kt * 64) * KVD + kvh * HD;
        #pragma unroll
        for (int t = 0; t < 4; t++) {
            int j = tid + t * 256;
            int r = j >> 4, c = j & 15;
            uint32_t o = swz256((uint32_t)(r * 256 + c * 16));
            size_t g = rb + (size_t)r * KVD + c * 8;
            cp16(st +         o, (const void*)(g_Kh + g));
            cp16(st + 16384 + o, (const void*)(g_Kl + g));
            cp16(st + 32768 + o, (const void*)(g_V + g));
        }
        CP_COMMIT();
    };
    loadKV(0);

    const int m0 = w * 16;
    const int qg0 = qb * 128 + m0 + (l >> 2);
    float O[16][4];
    #pragma unroll
    for (int f = 0; f < 16; f++)
        { O[f][0] = 0.f; O[f][1] = 0.f; O[f][2] = 0.f; O[f][3] = 0.f; }
    float mr0 = -1e30f, mr1 = -1e30f, sl0 = 0.f, sl1 = 0.f;

    for (int kt = 0; kt < NT; kt++) {
        if (kt + 1 < NT) {
            loadKV(kt + 1);
            asm volatile("cp.async.wait_group 1;\n");
        } else {
            asm volatile("cp.async.wait_group 0;\n");
        }
        __syncthreads();

        const uint32_t st = KV0 + (uint32_t)(kt & 1) * 49152;

        float s[8][4];
        #pragma unroll
        for (int nb = 0; nb < 8; nb++)
            { s[nb][0] = 0.f; s[nb][1] = 0.f; s[nb][2] = 0.f; s[nb][3] = 0.f; }

        #pragma unroll
        for (int ks = 0; ks < 8; ks++) {
            uint32_t aQh[4], aQl[4];
            uint32_t aaddr = Qh_s + swz256(
                (uint32_t)((m0 + (l & 15)) * 256 + ks * 32 + ((l & 16) ? 16 : 0)));
            LDSM_X4(aQh, aaddr);
            LDSM_X4(aQl, aaddr + 32768);
            #pragma unroll
            for (int nb2 = 0; nb2 < 4; nb2++) {
                uint32_t brow = (uint32_t)(nb2 * 16 + (l & 7) + ((l & 16) ? 8 : 0));
                uint32_t baddr = st + swz256(brow * 256 + ks * 32 + ((l & 8) ? 16 : 0));
                uint32_t bh[4], bl[4];
                LDSM_X4(bh, baddr);
                LDSM_X4(bl, baddr + 16384);
                MMA4(s[2*nb2],   aQh, bh[0], bh[1]);
                MMA4(s[2*nb2+1], aQh, bh[2], bh[3]);
                MMA4(s[2*nb2],   aQh, bl[0], bl[1]);
                MMA4(s[2*nb2+1], aQh, bl[2], bl[3]);
                MMA4(s[2*nb2],   aQl, bh[0], bh[1]);
                MMA4(s[2*nb2+1], aQl, bh[2], bh[3]);
            }
        }

        const int kgb = kt * 64 + (l & 3) * 2;
        float mx0 = -1e30f, mx1 = -1e30f;
        #pragma unroll
        for (int nb = 0; nb < 8; nb++) {
            int kg = kgb + nb * 8;
            if (kg     > qg0)     s[nb][0] = -1e30f;
            if (kg + 1 > qg0)     s[nb][1] = -1e30f;
            if (kg     > qg0 + 8) s[nb][2] = -1e30f;
            if (kg + 1 > qg0 + 8) s[nb][3] = -1e30f;
            mx0 = fmaxf(mx0, fmaxf(s[nb][0], s[nb][1]));
            mx1 = fmaxf(mx1, fmaxf(s[nb][2], s[nb][3]));
        }
        mx0 = fmaxf(mx0, __shfl_xor_sync(0xffffffffu, mx0, 1));
        mx0 = fmaxf(mx0, __shfl_xor_sync(0xffffffffu, mx0, 2));
        mx1 = fmaxf(mx1, __shfl_xor_sync(0xffffffffu, mx1, 1));
        mx1 = fmaxf(mx1, __shfl_xor_sync(0xffffffffu, mx1, 2));

        float mn0 = fmaxf(mr0, mx0), mn1 = fmaxf(mr1, mx1);
        float al0 = __expf(mr0 - mn0), al1 = __expf(mr1 - mn1);
        mr0 = mn0; mr1 = mn1;
        float sum0 = 0.f, sum1 = 0.f;
        #pragma unroll
        for (int nb = 0; nb < 8; nb++) {
            s[nb][0] = __expf(s[nb][0] - mn0);
            s[nb][1] = __expf(s[nb][1] - mn0);
            s[nb][2] = __expf(s[nb][2] - mn1);
            s[nb][3] = __expf(s[nb][3] - mn1);
            sum0 += s[nb][0] + s[nb][1];
            sum1 += s[nb][2] + s[nb][3];
        }
        sum0 += __shfl_xor_sync(0xffffffffu, sum0, 1);
        sum0 += __shfl_xor_sync(0xffffffffu, sum0, 2);
        sum1 += __shfl_xor_sync(0xffffffffu, sum1, 1);
        sum1 += __shfl_xor_sync(0xffffffffu, sum1, 2);
        sl0 = sl0 * al0 + sum0;
        sl1 = sl1 * al1 + sum1;
        #pragma unroll
        for (int f = 0; f < 16; f++) {
            O[f][0] *= al0; O[f][1] *= al0; O[f][2] *= al1; O[f][3] *= al1;
        }

        // ---- PV: P single fp16, V single fp16 (2 MMAs per pair) ----
        #pragma unroll
        for (int j = 0; j < 4; j++) {
            uint32_t pf[4];
            pf[0] = pkh(s[2*j][0],   s[2*j][1]);
            pf[1] = pkh(s[2*j][2],   s[2*j][3]);
            pf[2] = pkh(s[2*j+1][0], s[2*j+1][1]);
            pf[3] = pkh(s[2*j+1][2], s[2*j+1][3]);
            uint32_t vrow = (uint32_t)(j * 16 + (l & 7) + ((l & 8) ? 8 : 0));
            #pragma unroll
            for (int nb2 = 0; nb2 < 8; nb2++) {
                uint32_t vaddr = st + 32768 +
                    swz256(vrow * 256 + nb2 * 32 + ((l & 16) ? 16 : 0));
                uint32_t vh[4];
                LDSM_X4T(vh, vaddr);
                MMAH(O[2*nb2],   pf, vh[0], vh[1]);
                MMAH(O[2*nb2+1], pf, vh[2], vh[3]);
            }
        }
        __syncthreads();
    }

    // epilogue: normalize, scale x64, single fp16 for Wo GEMM
    const float i0 = 64.0f / sl0, i1 = 64.0f / sl1;
    size_t base0 = (size_t)(b * SS + qg0) * HID + (size_t)h * HD;
    size_t base1 = base0 + (size_t)8 * HID;
    #pragma unroll
    for (int nb = 0; nb < 16; nb++) {
        int col = nb * 8 + (l & 3) * 2;
        *(uint32_t*)(g_At + base0 + col) = pkh(O[nb][0] * i0, O[nb][1] * i0);
        *(uint32_t*)(g_At + base1 + col) = pkh(O[nb][2] * i1, O[nb][3] * i1);
    }
}

// ---------------------------------------------------------------------------
extern "C" void kernel_launch(void* const* d_in, const int* in_sizes, int n_in,
                              void* d_out, int out_size)
{
    (void)in_sizes; (void)n_in; (void)out_size;
    const float* x  = (const float*)d_in[0];
    const float* Wq = (const float*)d_in[1];
    const float* Wk = (const float*)d_in[2];
    const float* Wv = (const float*)d_in[3];
    const float* Wo = (const float*)d_in[4];
    float* out = (float*)d_out;

    __half *xh, *xl, *wh, *wl, *woh, *at;
    cudaGetSymbolAddress((void**)&xh, g_xh);   cudaGetSymbolAddress((void**)&xl, g_xl);
    cudaGetSymbolAddress((void**)&wh, g_Wh);   cudaGetSymbolAddress((void**)&wl, g_Wl);
    cudaGetSymbolAddress((void**)&woh, g_Woh);
    cudaGetSymbolAddress((void**)&at, g_At);

    cudaFuncSetAttribute(gemm_f16<1>, cudaFuncAttributeMaxDynamicSharedMemorySize, 196608);
    cudaFuncSetAttribute(gemm_f16<0>, cudaFuncAttributeMaxDynamicSharedMemorySize, 98304);
    cudaFuncSetAttribute(attn_mma, cudaFuncAttributeMaxDynamicSharedMemorySize, ATT_SMEM);

    rope_table_k<<<(SS * 64 + 255) / 256, 256>>>();
    cvt_xh<<<(MR * HID / 4 + 255) / 256, 256>>>(x, xh, xl, MR * HID / 4);
    cvt_qkv<<<(GK * (NQKV / 4) + 255) / 256, 256>>>(Wq, Wk, Wv);
    cvt_woh<<<(HID * HID / 4 + 255) / 256, 256>>>(Wo, woh, HID * HID / 4);

    // fused QKV projection + RoPE + split (Q,K 3-pass; V 2-pass)
    gemm_f16<1><<<dim3(NQKV / 128, MR / 128), 256, 196608>>>(
        xh, xl, wh, wl, nullptr, NQKV);

    attn_mma<<<dim3(SS / 128, NHQ, BB), 256, ATT_SMEM>>>();

    // output projection (1-pass Ah·Bh, 96KB smem -> 2 CTAs/SM)
    gemm_f16<0><<<dim3(HID / 128, MR / 128), 256, 98304>>>(
        at, nullptr, woh, nullptr, out, HID);
}